// round 1
// baseline (speedup 1.0000x reference)
#include <cuda_runtime.h>

#define NN   50000
#define EMAX 800000
#define DH   256

// ---------------- scratch (device globals; allocation-free) ----------------
__device__ __align__(16) int   g_deg[NN];
__device__ __align__(16) int   g_off[NN + 1];
__device__ __align__(16) int   g_cur[NN];
__device__ __align__(16) int   g_col[EMAX];
__device__ __align__(16) float g_mean1[(size_t)NN * 128];
__device__ __align__(16) float g_h1  [(size_t)NN * 256];
__device__ __align__(16) float g_mean2[(size_t)NN * 256];
__device__ __align__(16) float g_h2  [(size_t)NN * 256];

// ---------------- CSR build ----------------
__global__ void k_zero_deg() {
    int i = blockIdx.x * blockDim.x + threadIdx.x;
    if (i < NN) g_deg[i] = 0;
}

__global__ void k_count(const int* __restrict__ dst, int E) {
    int e = blockIdx.x * blockDim.x + threadIdx.x;
    if (e < E) atomicAdd(&g_deg[dst[e]], 1);
}

// single-block exclusive scan over g_deg -> g_off, g_cur
__global__ void k_scan(int E) {
    __shared__ int s[1024];
    __shared__ int s_carry;
    int t = threadIdx.x;
    if (t == 0) s_carry = 0;
    __syncthreads();
    for (int base = 0; base < NN; base += 1024) {
        int v = (base + t < NN) ? g_deg[base + t] : 0;
        s[t] = v;
        __syncthreads();
        for (int off = 1; off < 1024; off <<= 1) {
            int add = (t >= off) ? s[t - off] : 0;
            __syncthreads();
            s[t] += add;
            __syncthreads();
        }
        int incl  = s[t];
        int carry = s_carry;
        if (base + t < NN) {
            int excl = carry + incl - v;
            g_off[base + t] = excl;
            g_cur[base + t] = excl;
        }
        __syncthreads();
        if (t == 1023) s_carry = carry + incl;
        __syncthreads();
    }
    if (t == 0) g_off[NN] = E;
}

__global__ void k_fill(const int* __restrict__ src, const int* __restrict__ dst, int E) {
    int e = blockIdx.x * blockDim.x + threadIdx.x;
    if (e < E) {
        int p = atomicAdd(&g_cur[dst[e]], 1);
        g_col[p] = src[e];
    }
}

// ---------------- neighbor mean aggregation: one warp per dst node ----------------
// SEL==0: X = Xin (x, D=128) -> g_mean1 ; SEL==1: X = g_h1 (D=256) -> g_mean2
template <int D, int SEL>
__global__ void k_agg(const float* __restrict__ Xin) {
    const float* X   = (SEL == 0) ? Xin     : g_h1;
    float*       OUT = (SEL == 0) ? g_mean1 : g_mean2;

    int gw   = (blockIdx.x * blockDim.x + threadIdx.x) >> 5;
    int lane = threadIdx.x & 31;
    if (gw >= NN) return;

    constexpr int V = D / 128;  // float4s per lane
    float4 acc[V];
#pragma unroll
    for (int v = 0; v < V; v++) acc[v] = make_float4(0.f, 0.f, 0.f, 0.f);

    int s0 = g_off[gw], s1 = g_off[gw + 1];
    for (int i = s0; i < s1; i += 32) {
        int cnt = min(32, s1 - i);
        int my  = (lane < cnt) ? g_col[i + lane] : 0;
        for (int j = 0; j < cnt; j++) {
            int sidx = __shfl_sync(0xffffffffu, my, j);
            const float4* xr = (const float4*)(X + (size_t)sidx * D);
#pragma unroll
            for (int v = 0; v < V; v++) {
                float4 t = xr[v * 32 + lane];
                acc[v].x += t.x; acc[v].y += t.y; acc[v].z += t.z; acc[v].w += t.w;
            }
        }
    }
    int deg = s1 - s0;
    float inv = 1.0f / (float)max(deg, 1);
    float4* orow = (float4*)(OUT + (size_t)gw * D);
#pragma unroll
    for (int v = 0; v < V; v++) {
        float4 t;
        t.x = acc[v].x * inv; t.y = acc[v].y * inv;
        t.z = acc[v].z * inv; t.w = acc[v].w * inv;
        orow[v * 32 + lane] = t;
    }
}

// ---------------- fused two-input GEMM + bias + ReLU ----------------
// C[n, j] = relu( sum_k A1[n,k]*W1[j,k] + sum_k A2[n,k]*W2[j,k] + bias[j] )
// SEL==0: A1=g_mean1, A2=Xin(x),  C=g_h1, K=128
// SEL==1: A1=g_mean2, A2=g_h1,    C=g_h2, K=256
// Tile: BM=128, BN=64, BK=16; 256 threads; 8x4 per thread.
template <int K, int SEL>
__global__ void __launch_bounds__(256) k_gemm(const float* __restrict__ Xin,
                                              const float* __restrict__ W1,
                                              const float* __restrict__ W2,
                                              const float* __restrict__ bias) {
    const float* A1 = (SEL == 0) ? g_mean1 : g_mean2;
    const float* A2 = (SEL == 0) ? Xin     : g_h1;
    float*       C  = (SEL == 0) ? g_h1    : g_h2;

    __shared__ __align__(16) float As[16][128];
    __shared__ __align__(16) float Ws[16][64];

    int tid = threadIdx.x;
    int m0  = blockIdx.x * 128;
    int n0  = blockIdx.y * 64;
    int r0  = (tid >> 4) * 8;
    int c0  = (tid & 15) * 4;

    float acc[8][4];
#pragma unroll
    for (int i = 0; i < 8; i++)
#pragma unroll
        for (int j = 0; j < 4; j++) acc[i][j] = 0.f;

    int lm = tid >> 1;        // 0..127 : row within A tile
    int lk = (tid & 1) * 8;   // 0 or 8 : k-offset (8 floats)
    int wn = tid >> 2;        // 0..63  : output col within W tile
    int wk = (tid & 3) * 4;   // 0,4,8,12

#pragma unroll
    for (int ss = 0; ss < 2; ss++) {
        const float* A = ss ? A2 : A1;
        const float* W = ss ? W2 : W1;
        for (int k0 = 0; k0 < K; k0 += 16) {
            float4 av0, av1;
            int grow = m0 + lm;
            if (grow < NN) {
                const float* ap = A + (size_t)grow * K + k0 + lk;
                av0 = *(const float4*)ap;
                av1 = *(const float4*)(ap + 4);
            } else {
                av0 = make_float4(0.f, 0.f, 0.f, 0.f);
                av1 = av0;
            }
            float4 wv = *(const float4*)(W + (size_t)(n0 + wn) * K + k0 + wk);

            __syncthreads();
            As[lk + 0][lm] = av0.x; As[lk + 1][lm] = av0.y;
            As[lk + 2][lm] = av0.z; As[lk + 3][lm] = av0.w;
            As[lk + 4][lm] = av1.x; As[lk + 5][lm] = av1.y;
            As[lk + 6][lm] = av1.z; As[lk + 7][lm] = av1.w;
            Ws[wk + 0][wn] = wv.x; Ws[wk + 1][wn] = wv.y;
            Ws[wk + 2][wn] = wv.z; Ws[wk + 3][wn] = wv.w;
            __syncthreads();

#pragma unroll
            for (int kk = 0; kk < 16; kk++) {
                float4 a0 = *(const float4*)&As[kk][r0];
                float4 a1 = *(const float4*)&As[kk][r0 + 4];
                float4 w  = *(const float4*)&Ws[kk][c0];
                float am[8] = {a0.x, a0.y, a0.z, a0.w, a1.x, a1.y, a1.z, a1.w};
                float wm[4] = {w.x, w.y, w.z, w.w};
#pragma unroll
                for (int i = 0; i < 8; i++)
#pragma unroll
                    for (int j = 0; j < 4; j++) acc[i][j] += am[i] * wm[j];
            }
        }
    }

    float4 bv = *(const float4*)(bias + n0 + c0);
    float bb[4] = {bv.x, bv.y, bv.z, bv.w};
#pragma unroll
    for (int i = 0; i < 8; i++) {
        int row = m0 + r0 + i;
        if (row < NN) {
            float4 o;
            o.x = fmaxf(acc[i][0] + bb[0], 0.f);
            o.y = fmaxf(acc[i][1] + bb[1], 0.f);
            o.z = fmaxf(acc[i][2] + bb[2], 0.f);
            o.w = fmaxf(acc[i][3] + bb[3], 0.f);
            *(float4*)(C + (size_t)row * DH + n0 + c0) = o;
        }
    }
}

// ---------------- head: out[n] = dot(h2[n,:], head_w) + head_b ----------------
__global__ void k_head(const float* __restrict__ HW, const float* __restrict__ HB,
                       float* __restrict__ out) {
    int gw   = (blockIdx.x * blockDim.x + threadIdx.x) >> 5;
    int lane = threadIdx.x & 31;
    if (gw >= NN) return;
    const float4* h  = (const float4*)(g_h2 + (size_t)gw * 256);
    const float4* w4 = (const float4*)HW;
    float s = 0.f;
#pragma unroll
    for (int v = 0; v < 2; v++) {
        float4 a = h[v * 32 + lane];
        float4 b = w4[v * 32 + lane];
        s += a.x * b.x + a.y * b.y + a.z * b.z + a.w * b.w;
    }
#pragma unroll
    for (int o = 16; o; o >>= 1) s += __shfl_xor_sync(0xffffffffu, s, o);
    if (lane == 0) out[gw] = s + HB[0];
}

// ---------------- launch ----------------
extern "C" void kernel_launch(void* const* d_in, const int* in_sizes, int n_in,
                              void* d_out, int out_size) {
    const float* x   = (const float*)d_in[0];
    const int*   ei  = (const int*)d_in[1];
    const float* W1l = (const float*)d_in[2];
    const float* b1  = (const float*)d_in[3];
    const float* W1r = (const float*)d_in[4];
    const float* W2l = (const float*)d_in[5];
    const float* b2  = (const float*)d_in[6];
    const float* W2r = (const float*)d_in[7];
    const float* hw  = (const float*)d_in[8];
    const float* hb  = (const float*)d_in[9];
    float* out = (float*)d_out;

    int E = in_sizes[1] / 2;
    const int* srcp = ei;
    const int* dstp = ei + E;

    // CSR build (per launch; graph is identical for both layers)
    k_zero_deg<<<(NN + 255) / 256, 256>>>();
    k_count<<<(E + 255) / 256, 256>>>(dstp, E);
    k_scan<<<1, 1024>>>(E);
    k_fill<<<(E + 255) / 256, 256>>>(srcp, dstp, E);

    dim3 gemm_grid((NN + 127) / 128, 4);
    int  agg_blocks = (NN * 32 + 255) / 256;

    // Layer 1
    k_agg<128, 0><<<agg_blocks, 256>>>(x);
    k_gemm<128, 0><<<gemm_grid, 256>>>(x, W1l, W1r, b1);

    // Layer 2
    k_agg<256, 1><<<agg_blocks, 256>>>(nullptr);
    k_gemm<256, 1><<<gemm_grid, 256>>>(nullptr, W2l, W2r, b2);

    // Head
    k_head<<<agg_blocks, 256>>>(hw, hb, out);
}

// round 2
// speedup vs baseline: 1.6587x; 1.6587x over previous
#include <cuda_runtime.h>

#define NN   50000
#define EMAX 800000
#define DH   256

// ---------------- scratch (device globals; allocation-free) ----------------
__device__ __align__(16) int   g_deg[NN];
__device__ __align__(16) int   g_off[NN + 1];
__device__ __align__(16) int   g_cur[NN];
__device__ __align__(16) int   g_col[EMAX];
__device__ __align__(16) float g_mean1[(size_t)NN * 128];
__device__ __align__(16) float g_h1  [(size_t)NN * 256];
__device__ __align__(16) float g_mean2[(size_t)NN * 256];
__device__ __align__(16) float g_h2  [(size_t)NN * 256];

// ---------------- CSR build ----------------
__global__ void k_zero_deg() {
    int i = blockIdx.x * blockDim.x + threadIdx.x;
    if (i < NN) g_deg[i] = 0;
}

__global__ void k_count(const int* __restrict__ dst, int E) {
    int e = blockIdx.x * blockDim.x + threadIdx.x;
    if (e < E) atomicAdd(&g_deg[dst[e]], 1);
}

// single-block exclusive scan over g_deg -> g_off, g_cur
__global__ void k_scan(int E) {
    __shared__ int s[1024];
    __shared__ int s_carry;
    int t = threadIdx.x;
    if (t == 0) s_carry = 0;
    __syncthreads();
    for (int base = 0; base < NN; base += 1024) {
        int v = (base + t < NN) ? g_deg[base + t] : 0;
        s[t] = v;
        __syncthreads();
        for (int off = 1; off < 1024; off <<= 1) {
            int add = (t >= off) ? s[t - off] : 0;
            __syncthreads();
            s[t] += add;
            __syncthreads();
        }
        int incl  = s[t];
        int carry = s_carry;
        if (base + t < NN) {
            int excl = carry + incl - v;
            g_off[base + t] = excl;
            g_cur[base + t] = excl;
        }
        __syncthreads();
        if (t == 1023) s_carry = carry + incl;
        __syncthreads();
    }
    if (t == 0) g_off[NN] = E;
}

__global__ void k_fill(const int* __restrict__ src, const int* __restrict__ dst, int E) {
    int e = blockIdx.x * blockDim.x + threadIdx.x;
    if (e < E) {
        int p = atomicAdd(&g_cur[dst[e]], 1);
        g_col[p] = src[e];
    }
}

// ---------------- neighbor mean aggregation: one warp per dst node ----------------
template <int D, int SEL>
__global__ void k_agg(const float* __restrict__ Xin) {
    const float* X   = (SEL == 0) ? Xin     : g_h1;
    float*       OUT = (SEL == 0) ? g_mean1 : g_mean2;

    int gw   = (blockIdx.x * blockDim.x + threadIdx.x) >> 5;
    int lane = threadIdx.x & 31;
    if (gw >= NN) return;

    constexpr int V = D / 128;  // float4s per lane
    float4 acc[V];
#pragma unroll
    for (int v = 0; v < V; v++) acc[v] = make_float4(0.f, 0.f, 0.f, 0.f);

    int s0 = g_off[gw], s1 = g_off[gw + 1];
    for (int i = s0; i < s1; i += 32) {
        int cnt = min(32, s1 - i);
        int my  = (lane < cnt) ? g_col[i + lane] : 0;
        for (int j = 0; j < cnt; j++) {
            int sidx = __shfl_sync(0xffffffffu, my, j);
            const float4* xr = (const float4*)(X + (size_t)sidx * D);
#pragma unroll
            for (int v = 0; v < V; v++) {
                float4 t = xr[v * 32 + lane];
                acc[v].x += t.x; acc[v].y += t.y; acc[v].z += t.z; acc[v].w += t.w;
            }
        }
    }
    int deg = s1 - s0;
    float inv = 1.0f / (float)max(deg, 1);
    float4* orow = (float4*)(OUT + (size_t)gw * D);
#pragma unroll
    for (int v = 0; v < V; v++) {
        float4 t;
        t.x = acc[v].x * inv; t.y = acc[v].y * inv;
        t.z = acc[v].z * inv; t.w = acc[v].w * inv;
        orow[v * 32 + lane] = t;
    }
}

// ---------------- tf32 tensor-core fused two-input GEMM + bias + ReLU -------
// C[n, j] = relu( sum_k A1[n,k]*W1[j,k] + sum_k A2[n,k]*W2[j,k] + bias[j] )
// BM=128, BN=128, BK=16; 8 warps (2 M x 4 N); warp tile 64x32 via m16n8k8.tf32
__device__ __forceinline__ float to_tf32(float x) {
    float y;
    asm("cvt.rna.tf32.f32 %0, %1;" : "=f"(y) : "f"(x));
    return y;
}

__device__ __forceinline__ void mma_tf32(float c[4], const float a[4], const float b[2]) {
    asm volatile(
        "mma.sync.aligned.m16n8k8.row.col.f32.tf32.tf32.f32 "
        "{%0,%1,%2,%3}, {%4,%5,%6,%7}, {%8,%9}, {%0,%1,%2,%3};\n"
        : "+f"(c[0]), "+f"(c[1]), "+f"(c[2]), "+f"(c[3])
        : "f"(a[0]), "f"(a[1]), "f"(a[2]), "f"(a[3]), "f"(b[0]), "f"(b[1]));
}

template <int K, int SEL>
__global__ void __launch_bounds__(256) k_gemm_tc(const float* __restrict__ Xin,
                                                const float* __restrict__ W1,
                                                const float* __restrict__ W2,
                                                const float* __restrict__ bias) {
    const float* A1 = (SEL == 0) ? g_mean1 : g_mean2;
    const float* A2 = (SEL == 0) ? Xin     : g_h1;
    float*       C  = (SEL == 0) ? g_h1    : g_h2;

    __shared__ __align__(16) float As[128][20];  // [row][k], pad
    __shared__ __align__(16) float Ws[128][20];  // [n]  [k], pad

    const int tid  = threadIdx.x;
    const int warp = tid >> 5;
    const int lane = tid & 31;
    const int g    = lane >> 2;   // 0..7
    const int t    = lane & 3;    // 0..3

    const int m0 = blockIdx.x * 128;
    const int n0 = blockIdx.y * 128;
    const int wm = warp >> 2;     // 0..1 : 64-row slab
    const int wn = warp & 3;      // 0..3 : 32-col slab

    float acc[4][4][4];
#pragma unroll
    for (int i = 0; i < 4; i++)
#pragma unroll
        for (int j = 0; j < 4; j++)
#pragma unroll
            for (int c = 0; c < 4; c++) acc[i][j][c] = 0.f;

    const int lrow = tid >> 1;          // 0..127
    const int lk   = (tid & 1) * 8;     // 0 or 8

#pragma unroll
    for (int ss = 0; ss < 2; ss++) {
        const float* A = ss ? A2 : A1;
        const float* W = ss ? W2 : W1;
        for (int k0 = 0; k0 < K; k0 += 16) {
            // global -> reg
            float4 av0, av1;
            int grow = m0 + lrow;
            if (grow < NN) {
                const float* ap = A + (size_t)grow * K + k0 + lk;
                av0 = *(const float4*)ap;
                av1 = *(const float4*)(ap + 4);
            } else {
                av0 = make_float4(0.f, 0.f, 0.f, 0.f);
                av1 = av0;
            }
            const float* wp = W + (size_t)(n0 + lrow) * K + k0 + lk;
            float4 wv0 = *(const float4*)wp;
            float4 wv1 = *(const float4*)(wp + 4);

            __syncthreads();
            As[lrow][lk + 0] = to_tf32(av0.x); As[lrow][lk + 1] = to_tf32(av0.y);
            As[lrow][lk + 2] = to_tf32(av0.z); As[lrow][lk + 3] = to_tf32(av0.w);
            As[lrow][lk + 4] = to_tf32(av1.x); As[lrow][lk + 5] = to_tf32(av1.y);
            As[lrow][lk + 6] = to_tf32(av1.z); As[lrow][lk + 7] = to_tf32(av1.w);
            Ws[lrow][lk + 0] = to_tf32(wv0.x); Ws[lrow][lk + 1] = to_tf32(wv0.y);
            Ws[lrow][lk + 2] = to_tf32(wv0.z); Ws[lrow][lk + 3] = to_tf32(wv0.w);
            Ws[lrow][lk + 4] = to_tf32(wv1.x); Ws[lrow][lk + 5] = to_tf32(wv1.y);
            Ws[lrow][lk + 6] = to_tf32(wv1.z); Ws[lrow][lk + 7] = to_tf32(wv1.w);
            __syncthreads();

#pragma unroll
            for (int ks = 0; ks < 2; ks++) {
                const int kb = ks * 8;
                float b[4][2];
#pragma unroll
                for (int nt = 0; nt < 4; nt++) {
                    int col = wn * 32 + nt * 8 + g;
                    b[nt][0] = Ws[col][kb + t];
                    b[nt][1] = Ws[col][kb + t + 4];
                }
#pragma unroll
                for (int mt = 0; mt < 4; mt++) {
                    float a[4];
                    int r = wm * 64 + mt * 16 + g;
                    a[0] = As[r][kb + t];
                    a[1] = As[r + 8][kb + t];
                    a[2] = As[r][kb + t + 4];
                    a[3] = As[r + 8][kb + t + 4];
#pragma unroll
                    for (int nt = 0; nt < 4; nt++)
                        mma_tf32(acc[mt][nt], a, b[nt]);
                }
            }
        }
    }

    // epilogue: bias + relu, float2 stores
#pragma unroll
    for (int mt = 0; mt < 4; mt++) {
#pragma unroll
        for (int nt = 0; nt < 4; nt++) {
            int col = n0 + wn * 32 + nt * 8 + 2 * t;
            float b0 = bias[col], b1 = bias[col + 1];
            int r0 = m0 + wm * 64 + mt * 16 + g;
            if (r0 < NN) {
                float2 o;
                o.x = fmaxf(acc[mt][nt][0] + b0, 0.f);
                o.y = fmaxf(acc[mt][nt][1] + b1, 0.f);
                *(float2*)(C + (size_t)r0 * DH + col) = o;
            }
            int r1 = r0 + 8;
            if (r1 < NN) {
                float2 o;
                o.x = fmaxf(acc[mt][nt][2] + b0, 0.f);
                o.y = fmaxf(acc[mt][nt][3] + b1, 0.f);
                *(float2*)(C + (size_t)r1 * DH + col) = o;
            }
        }
    }
}

// ---------------- head: out[n] = dot(h2[n,:], head_w) + head_b ----------------
__global__ void k_head(const float* __restrict__ HW, const float* __restrict__ HB,
                       float* __restrict__ out) {
    int gw   = (blockIdx.x * blockDim.x + threadIdx.x) >> 5;
    int lane = threadIdx.x & 31;
    if (gw >= NN) return;
    const float4* h  = (const float4*)(g_h2 + (size_t)gw * 256);
    const float4* w4 = (const float4*)HW;
    float s = 0.f;
#pragma unroll
    for (int v = 0; v < 2; v++) {
        float4 a = h[v * 32 + lane];
        float4 b = w4[v * 32 + lane];
        s += a.x * b.x + a.y * b.y + a.z * b.z + a.w * b.w;
    }
#pragma unroll
    for (int o = 16; o; o >>= 1) s += __shfl_xor_sync(0xffffffffu, s, o);
    if (lane == 0) out[gw] = s + HB[0];
}

// ---------------- launch ----------------
extern "C" void kernel_launch(void* const* d_in, const int* in_sizes, int n_in,
                              void* d_out, int out_size) {
    const float* x   = (const float*)d_in[0];
    const int*   ei  = (const int*)d_in[1];
    const float* W1l = (const float*)d_in[2];
    const float* b1  = (const float*)d_in[3];
    const float* W1r = (const float*)d_in[4];
    const float* W2l = (const float*)d_in[5];
    const float* b2  = (const float*)d_in[6];
    const float* W2r = (const float*)d_in[7];
    const float* hw  = (const float*)d_in[8];
    const float* hb  = (const float*)d_in[9];
    float* out = (float*)d_out;

    int E = in_sizes[1] / 2;
    const int* srcp = ei;
    const int* dstp = ei + E;

    // CSR build (per launch; graph is identical for both layers)
    k_zero_deg<<<(NN + 255) / 256, 256>>>();
    k_count<<<(E + 255) / 256, 256>>>(dstp, E);
    k_scan<<<1, 1024>>>(E);
    k_fill<<<(E + 255) / 256, 256>>>(srcp, dstp, E);

    dim3 gemm_grid((NN + 127) / 128, 2);
    int  agg_blocks = (NN * 32 + 255) / 256;

    // Layer 1
    k_agg<128, 0><<<agg_blocks, 256>>>(x);
    k_gemm_tc<128, 0><<<gemm_grid, 256>>>(x, W1l, W1r, b1);

    // Layer 2
    k_agg<256, 1><<<agg_blocks, 256>>>(nullptr);
    k_gemm_tc<256, 1><<<gemm_grid, 256>>>(nullptr, W2l, W2r, b2);

    // Head
    k_head<<<agg_blocks, 256>>>(hw, hb, out);
}

// round 4
// speedup vs baseline: 1.8078x; 1.0899x over previous
#include <cuda_runtime.h>
#include <cstdint>

#define NN   50000
#define EMAX 800000
#define DH   256

// ---------------- scratch (device globals; allocation-free) ----------------
__device__ __align__(16) int   g_deg[NN];
__device__ __align__(16) int   g_off[NN + 1];
__device__ __align__(16) int   g_cur[NN];
__device__ __align__(16) int   g_col[EMAX];
__device__ __align__(16) float g_xr  [(size_t)NN * 128];   // x rounded to tf32
__device__ __align__(16) float g_w1l[256 * 128];
__device__ __align__(16) float g_w1r[256 * 128];
__device__ __align__(16) float g_w2l[256 * 256];
__device__ __align__(16) float g_w2r[256 * 256];
__device__ __align__(16) float g_mean1[(size_t)NN * 128];
__device__ __align__(16) float g_h1  [(size_t)NN * 256];
__device__ __align__(16) float g_mean2[(size_t)NN * 256];
__device__ __align__(16) float g_h2  [(size_t)NN * 256];

// ---------------- helpers ----------------
__device__ __forceinline__ float to_tf32(float x) {
    float y;
    asm("cvt.rna.tf32.f32 %0, %1;" : "=f"(y) : "f"(x));
    return y;
}

__device__ __forceinline__ uint32_t smem_u32(const void* p) {
    uint32_t a;
    asm("{ .reg .u64 t; cvta.to.shared.u64 t, %1; cvt.u32.u64 %0, t; }" : "=r"(a) : "l"(p));
    return a;
}

__device__ __forceinline__ void cp16(uint32_t dst, const void* src, bool v) {
    int sz = v ? 16 : 0;
    asm volatile("cp.async.cg.shared.global [%0], [%1], 16, %2;\n"
                 :: "r"(dst), "l"(src), "r"(sz) : "memory");
}

__device__ __forceinline__ void mma_tf32(float c[4], const float a[4], const float b[2]) {
    asm volatile(
        "mma.sync.aligned.m16n8k8.row.col.f32.tf32.tf32.f32 "
        "{%0,%1,%2,%3}, {%4,%5,%6,%7}, {%8,%9}, {%0,%1,%2,%3};\n"
        : "+f"(c[0]), "+f"(c[1]), "+f"(c[2]), "+f"(c[3])
        : "f"(a[0]), "f"(a[1]), "f"(a[2]), "f"(a[3]), "f"(b[0]), "f"(b[1]));
}

// ---------------- pre-rounding kernels ----------------
__global__ void k_round_x(const float* __restrict__ x) {
    int i = blockIdx.x * blockDim.x + threadIdx.x;
    if (i < NN * 128 / 4) {
        float4 v = ((const float4*)x)[i];
        v.x = to_tf32(v.x); v.y = to_tf32(v.y); v.z = to_tf32(v.z); v.w = to_tf32(v.w);
        ((float4*)g_xr)[i] = v;
    }
}

__global__ void k_round_w(const float* __restrict__ W1l, const float* __restrict__ W1r,
                          const float* __restrict__ W2l, const float* __restrict__ W2r) {
    int i = blockIdx.x * blockDim.x + threadIdx.x;
    if (i < 256 * 128) {
        g_w1l[i] = to_tf32(W1l[i]);
        g_w1r[i] = to_tf32(W1r[i]);
    }
    if (i < 256 * 256) {
        g_w2l[i] = to_tf32(W2l[i]);
        g_w2r[i] = to_tf32(W2r[i]);
    }
}

// ---------------- CSR build ----------------
__global__ void k_zero_deg() {
    int i = blockIdx.x * blockDim.x + threadIdx.x;
    if (i < NN) g_deg[i] = 0;
}

__global__ void k_count(const int* __restrict__ dst, int E) {
    int e = blockIdx.x * blockDim.x + threadIdx.x;
    if (e < E) atomicAdd(&g_deg[dst[e]], 1);
}

// single-block exclusive scan via warp shuffles
__global__ void k_scan(int E) {
    __shared__ int wsum[32];
    __shared__ int s_carry;
    int t = threadIdx.x, lane = t & 31, w = t >> 5;
    if (t == 0) s_carry = 0;
    __syncthreads();
    for (int base = 0; base < NN; base += 1024) {
        int v = (base + t < NN) ? g_deg[base + t] : 0;
        int x = v;
#pragma unroll
        for (int o = 1; o < 32; o <<= 1) {
            int y = __shfl_up_sync(0xffffffffu, x, o);
            if (lane >= o) x += y;
        }
        if (lane == 31) wsum[w] = x;
        __syncthreads();
        if (w == 0) {
            int y = wsum[lane];
            int z = y;
#pragma unroll
            for (int o = 1; o < 32; o <<= 1) {
                int q = __shfl_up_sync(0xffffffffu, z, o);
                if (lane >= o) z += q;
            }
            wsum[lane] = z - y;  // exclusive offsets of warp sums
        }
        __syncthreads();
        int incl  = x + wsum[w];
        int carry = s_carry;
        if (base + t < NN) {
            int excl = carry + incl - v;
            g_off[base + t] = excl;
            g_cur[base + t] = excl;
        }
        __syncthreads();
        if (t == 1023) s_carry = carry + incl;
        __syncthreads();
    }
    if (t == 0) g_off[NN] = E;
}

__global__ void k_fill(const int* __restrict__ src, const int* __restrict__ dst, int E) {
    int e = blockIdx.x * blockDim.x + threadIdx.x;
    if (e < E) {
        int p = atomicAdd(&g_cur[dst[e]], 1);
        g_col[p] = src[e];
    }
}

// ---------------- aggregation: one warp per dst node; 4-neighbor unroll ----------
template <int D, int SEL>
__global__ void k_agg() {
    const float* X   = (SEL == 0) ? g_xr    : g_h1;
    float*       OUT = (SEL == 0) ? g_mean1 : g_mean2;

    int gw   = (blockIdx.x * blockDim.x + threadIdx.x) >> 5;
    int lane = threadIdx.x & 31;
    if (gw >= NN) return;

    constexpr int V = D / 128;
    float4 acc[V];
#pragma unroll
    for (int v = 0; v < V; v++) acc[v] = make_float4(0.f, 0.f, 0.f, 0.f);

    int s0 = g_off[gw], s1 = g_off[gw + 1];
    for (int i = s0; i < s1; i += 32) {
        int cnt = min(32, s1 - i);
        int my  = (lane < cnt) ? g_col[i + lane] : 0;
        int j = 0;
        for (; j + 4 <= cnt; j += 4) {
            int i0 = __shfl_sync(0xffffffffu, my, j + 0);
            int i1 = __shfl_sync(0xffffffffu, my, j + 1);
            int i2 = __shfl_sync(0xffffffffu, my, j + 2);
            int i3 = __shfl_sync(0xffffffffu, my, j + 3);
            const float4* p0 = (const float4*)(X + (size_t)i0 * D);
            const float4* p1 = (const float4*)(X + (size_t)i1 * D);
            const float4* p2 = (const float4*)(X + (size_t)i2 * D);
            const float4* p3 = (const float4*)(X + (size_t)i3 * D);
#pragma unroll
            for (int v = 0; v < V; v++) {
                float4 t0 = p0[v * 32 + lane];
                float4 t1 = p1[v * 32 + lane];
                float4 t2 = p2[v * 32 + lane];
                float4 t3 = p3[v * 32 + lane];
                acc[v].x += t0.x + t1.x + t2.x + t3.x;
                acc[v].y += t0.y + t1.y + t2.y + t3.y;
                acc[v].z += t0.z + t1.z + t2.z + t3.z;
                acc[v].w += t0.w + t1.w + t2.w + t3.w;
            }
        }
        for (; j < cnt; j++) {
            int sidx = __shfl_sync(0xffffffffu, my, j);
            const float4* xr = (const float4*)(X + (size_t)sidx * D);
#pragma unroll
            for (int v = 0; v < V; v++) {
                float4 t = xr[v * 32 + lane];
                acc[v].x += t.x; acc[v].y += t.y; acc[v].z += t.z; acc[v].w += t.w;
            }
        }
    }
    int deg = s1 - s0;
    float inv = 1.0f / (float)max(deg, 1);
    float4* orow = (float4*)(OUT + (size_t)gw * D);
#pragma unroll
    for (int v = 0; v < V; v++) {
        float4 t;
        t.x = to_tf32(acc[v].x * inv); t.y = to_tf32(acc[v].y * inv);
        t.z = to_tf32(acc[v].z * inv); t.w = to_tf32(acc[v].w * inv);
        orow[v * 32 + lane] = t;
    }
}

// ---------------- tf32 mma.sync fused two-input GEMM + bias + ReLU ----------------
// C = relu(A1@W1^T + A2@W2^T + bias). All inputs pre-rounded to tf32 (HW
// truncation in mma.sync is then lossless). BM=128,BN=128,BK=32; 8 warps 2x4;
// warp tile 64x32 via m16n8k8; cp.async double-buffered smem.
#define PADK 36
#define STAGE_FLOATS (2 * 128 * PADK)       // A + W per stage
#define GEMM_SMEM (2 * STAGE_FLOATS * 4)    // 73728 B

template <int K, int SEL>
__device__ __forceinline__ void load_chunk(int c, int m0, int n0, uint32_t sb, int tid) {
    constexpr int NCH = (2 * K) / 32;
    const float* A1 = (SEL == 0) ? g_mean1 : g_mean2;
    const float* A2 = (SEL == 0) ? g_xr    : g_h1;
    const float* W1 = (SEL == 0) ? g_w1l   : g_w2l;
    const float* W2 = (SEL == 0) ? g_w1r   : g_w2r;

    int st = c & 1;
    int ss = (c >= NCH / 2);
    int k0 = (c - ss * (NCH / 2)) * 32;
    const float* A = ss ? A2 : A1;
    const float* W = ss ? W2 : W1;

    int row  = tid >> 1;         // 0..127
    int half = tid & 1;          // 0/1 -> 16 floats

    uint32_t base = sb + (uint32_t)st * (STAGE_FLOATS * 4);
    uint32_t adst = base + row * (PADK * 4) + half * 64;
    uint32_t wdst = adst + 128 * PADK * 4;

    int  arow = m0 + row;
    bool v    = (arow < NN);
    int  ar   = v ? arow : 0;
    const float* asrc = A + (size_t)ar * K + k0 + half * 16;
    const float* wsrc = W + (size_t)(n0 + row) * K + k0 + half * 16;
#pragma unroll
    for (int q = 0; q < 4; q++) {
        cp16(adst + q * 16, asrc + q * 4, v);
        cp16(wdst + q * 16, wsrc + q * 4, true);
    }
    asm volatile("cp.async.commit_group;" ::: "memory");
}

template <int K, int SEL>
__global__ void __launch_bounds__(256) k_gemm_tc(const float* __restrict__ bias) {
    float* C = (SEL == 0) ? g_h1 : g_h2;
    constexpr int  NCH   = (2 * K) / 32;
    constexpr bool ROUND = (SEL == 0);

    extern __shared__ __align__(16) float smem[];
    uint32_t sb = smem_u32(smem);

    const int tid  = threadIdx.x;
    const int warp = tid >> 5;
    const int lane = tid & 31;
    const int g    = lane >> 2;
    const int t    = lane & 3;
    const int m0   = blockIdx.x * 128;
    const int n0   = blockIdx.y * 128;
    const int wm   = warp >> 2;   // 0..1
    const int wn   = warp & 3;    // 0..3

    float acc[4][4][4];
#pragma unroll
    for (int i = 0; i < 4; i++)
#pragma unroll
        for (int j = 0; j < 4; j++)
#pragma unroll
            for (int c = 0; c < 4; c++) acc[i][j][c] = 0.f;

    load_chunk<K, SEL>(0, m0, n0, sb, tid);

    for (int c = 0; c < NCH; c++) {
        if (c + 1 < NCH) {
            load_chunk<K, SEL>(c + 1, m0, n0, sb, tid);
            asm volatile("cp.async.wait_group 1;" ::: "memory");
        } else {
            asm volatile("cp.async.wait_group 0;" ::: "memory");
        }
        __syncthreads();

        const float* As = smem + (c & 1) * STAGE_FLOATS;
        const float* Ws = As + 128 * PADK;

#pragma unroll
        for (int ks = 0; ks < 4; ks++) {
            const int kb = ks * 8;
            float b[4][2];
#pragma unroll
            for (int nt = 0; nt < 4; nt++) {
                int col = wn * 32 + nt * 8 + g;
                b[nt][0] = Ws[col * PADK + kb + t];
                b[nt][1] = Ws[col * PADK + kb + t + 4];
            }
#pragma unroll
            for (int mt = 0; mt < 4; mt++) {
                float a[4];
                int r = wm * 64 + mt * 16 + g;
                a[0] = As[r * PADK + kb + t];
                a[1] = As[(r + 8) * PADK + kb + t];
                a[2] = As[r * PADK + kb + t + 4];
                a[3] = As[(r + 8) * PADK + kb + t + 4];
#pragma unroll
                for (int nt = 0; nt < 4; nt++)
                    mma_tf32(acc[mt][nt], a, b[nt]);
            }
        }
        __syncthreads();  // done reading this stage before it is overwritten
    }

    // epilogue: bias + relu (+tf32 round for h1), float2 stores
#pragma unroll
    for (int mt = 0; mt < 4; mt++) {
#pragma unroll
        for (int nt = 0; nt < 4; nt++) {
            int col = n0 + wn * 32 + nt * 8 + 2 * t;
            float b0 = bias[col], b1 = bias[col + 1];
            int r0 = m0 + wm * 64 + mt * 16 + g;
            if (r0 < NN) {
                float2 o;
                o.x = fmaxf(acc[mt][nt][0] + b0, 0.f);
                o.y = fmaxf(acc[mt][nt][1] + b1, 0.f);
                if (ROUND) { o.x = to_tf32(o.x); o.y = to_tf32(o.y); }
                *(float2*)(C + (size_t)r0 * DH + col) = o;
            }
            int r1 = r0 + 8;
            if (r1 < NN) {
                float2 o;
                o.x = fmaxf(acc[mt][nt][2] + b0, 0.f);
                o.y = fmaxf(acc[mt][nt][3] + b1, 0.f);
                if (ROUND) { o.x = to_tf32(o.x); o.y = to_tf32(o.y); }
                *(float2*)(C + (size_t)r1 * DH + col) = o;
            }
        }
    }
}

// ---------------- head ----------------
__global__ void k_head(const float* __restrict__ HW, const float* __restrict__ HB,
                       float* __restrict__ out) {
    int gw   = (blockIdx.x * blockDim.x + threadIdx.x) >> 5;
    int lane = threadIdx.x & 31;
    if (gw >= NN) return;
    const float4* h  = (const float4*)(g_h2 + (size_t)gw * 256);
    const float4* w4 = (const float4*)HW;
    float s = 0.f;
#pragma unroll
    for (int v = 0; v < 2; v++) {
        float4 a = h[v * 32 + lane];
        float4 b = w4[v * 32 + lane];
        s += a.x * b.x + a.y * b.y + a.z * b.z + a.w * b.w;
    }
#pragma unroll
    for (int o = 16; o; o >>= 1) s += __shfl_xor_sync(0xffffffffu, s, o);
    if (lane == 0) out[gw] = s + HB[0];
}

// ---------------- launch ----------------
extern "C" void kernel_launch(void* const* d_in, const int* in_sizes, int n_in,
                              void* d_out, int out_size) {
    const float* x   = (const float*)d_in[0];
    const int*   ei  = (const int*)d_in[1];
    const float* W1l = (const float*)d_in[2];
    const float* b1  = (const float*)d_in[3];
    const float* W1r = (const float*)d_in[4];
    const float* W2l = (const float*)d_in[5];
    const float* b2  = (const float*)d_in[6];
    const float* W2r = (const float*)d_in[7];
    const float* hw  = (const float*)d_in[8];
    const float* hb  = (const float*)d_in[9];
    float* out = (float*)d_out;

    int E = in_sizes[1] / 2;
    const int* srcp = ei;
    const int* dstp = ei + E;

    cudaFuncSetAttribute(k_gemm_tc<128, 0>, cudaFuncAttributeMaxDynamicSharedMemorySize, GEMM_SMEM);
    cudaFuncSetAttribute(k_gemm_tc<256, 1>, cudaFuncAttributeMaxDynamicSharedMemorySize, GEMM_SMEM);

    // pre-round inputs to exact tf32
    k_round_x<<<(NN * 128 / 4 + 255) / 256, 256>>>(x);
    k_round_w<<<(256 * 256 + 255) / 256, 256>>>(W1l, W1r, W2l, W2r);

    // CSR build
    k_zero_deg<<<(NN + 255) / 256, 256>>>();
    k_count<<<(E + 255) / 256, 256>>>(dstp, E);
    k_scan<<<1, 1024>>>(E);
    k_fill<<<(E + 255) / 256, 256>>>(srcp, dstp, E);

    dim3 gemm_grid((NN + 127) / 128, 2);
    int  agg_blocks = (NN * 32 + 255) / 256;

    // Layer 1
    k_agg<128, 0><<<agg_blocks, 256>>>();
    k_gemm_tc<128, 0><<<gemm_grid, 256, GEMM_SMEM>>>(b1);

    // Layer 2
    k_agg<256, 1><<<agg_blocks, 256>>>();
    k_gemm_tc<256, 1><<<gemm_grid, 256, GEMM_SMEM>>>(b2);

    // Head
    k_head<<<agg_blocks, 256>>>(hw, hb, out);
}

// round 6
// speedup vs baseline: 2.7992x; 1.5484x over previous
#include <cuda_runtime.h>
#include <cuda_fp16.h>
#include <cstdint>

#define NN   50000
#define EMAX 800000
#define DH   256

// ---------------- scratch (device globals; allocation-free) ----------------
__device__ __align__(16) int    g_deg[NN];
__device__ __align__(16) int    g_off[NN + 1];
__device__ __align__(16) int    g_cur[NN];
__device__ __align__(16) int    g_col[EMAX];
__device__ __align__(16) __half g_xh  [(size_t)NN * 128];   // x in fp16
__device__ __align__(16) __half g_w1lh[256 * 128];
__device__ __align__(16) __half g_w1rh[256 * 128];
__device__ __align__(16) __half g_w2lh[256 * 256];
__device__ __align__(16) __half g_w2rh[256 * 256];
__device__ __align__(16) __half g_m1h [(size_t)NN * 128];
__device__ __align__(16) __half g_h1h [(size_t)NN * 256];
__device__ __align__(16) __half g_m2h [(size_t)NN * 256];
__device__ __align__(16) __half g_h2h [(size_t)NN * 256];

// ---------------- helpers ----------------
__device__ __forceinline__ uint32_t smem_u32(const void* p) {
    uint32_t a;
    asm("{ .reg .u64 t; cvta.to.shared.u64 t, %1; cvt.u32.u64 %0, t; }" : "=r"(a) : "l"(p));
    return a;
}

__device__ __forceinline__ void cp16(uint32_t dst, const void* src, bool v) {
    int sz = v ? 16 : 0;
    asm volatile("cp.async.cg.shared.global [%0], [%1], 16, %2;\n"
                 :: "r"(dst), "l"(src), "r"(sz) : "memory");
}

__device__ __forceinline__ void mma_f16(float c[4], const uint32_t a[4], const uint32_t b[2]) {
    asm volatile(
        "mma.sync.aligned.m16n8k16.row.col.f32.f16.f16.f32 "
        "{%0,%1,%2,%3}, {%4,%5,%6,%7}, {%8,%9}, {%0,%1,%2,%3};\n"
        : "+f"(c[0]), "+f"(c[1]), "+f"(c[2]), "+f"(c[3])
        : "r"(a[0]), "r"(a[1]), "r"(a[2]), "r"(a[3]), "r"(b[0]), "r"(b[1]));
}

// ---------------- conversion kernels ----------------
__global__ void k_round_x(const float* __restrict__ x) {
    int i = blockIdx.x * blockDim.x + threadIdx.x;
    if (i < NN) g_deg[i] = 0;                 // fold CSR zeroing in here
    if (i < NN * 128 / 4) {
        float4 v = ((const float4*)x)[i];
        __half2 h0 = __floats2half2_rn(v.x, v.y);
        __half2 h1 = __floats2half2_rn(v.z, v.w);
        uint2 o;
        o.x = *(uint32_t*)&h0;
        o.y = *(uint32_t*)&h1;
        ((uint2*)g_xh)[i] = o;
    }
}

__global__ void k_round_w(const float* __restrict__ W1l, const float* __restrict__ W1r,
                          const float* __restrict__ W2l, const float* __restrict__ W2r) {
    int i = blockIdx.x * blockDim.x + threadIdx.x;
    if (i < 256 * 128) {
        g_w1lh[i] = __float2half_rn(W1l[i]);
        g_w1rh[i] = __float2half_rn(W1r[i]);
    }
    if (i < 256 * 256) {
        g_w2lh[i] = __float2half_rn(W2l[i]);
        g_w2rh[i] = __float2half_rn(W2r[i]);
    }
}

// ---------------- CSR build ----------------
__global__ void k_count(const int* __restrict__ dst, int E) {
    int e = blockIdx.x * blockDim.x + threadIdx.x;
    if (e < E) atomicAdd(&g_deg[dst[e]], 1);
}

__global__ void k_scan(int E) {
    __shared__ int wsum[32];
    __shared__ int s_carry;
    int t = threadIdx.x, lane = t & 31, w = t >> 5;
    if (t == 0) s_carry = 0;
    __syncthreads();
    for (int base = 0; base < NN; base += 1024) {
        int v = (base + t < NN) ? g_deg[base + t] : 0;
        int x = v;
#pragma unroll
        for (int o = 1; o < 32; o <<= 1) {
            int y = __shfl_up_sync(0xffffffffu, x, o);
            if (lane >= o) x += y;
        }
        if (lane == 31) wsum[w] = x;
        __syncthreads();
        if (w == 0) {
            int y = wsum[lane];
            int z = y;
#pragma unroll
            for (int o = 1; o < 32; o <<= 1) {
                int q = __shfl_up_sync(0xffffffffu, z, o);
                if (lane >= o) z += q;
            }
            wsum[lane] = z - y;
        }
        __syncthreads();
        int incl  = x + wsum[w];
        int carry = s_carry;
        if (base + t < NN) {
            int excl = carry + incl - v;
            g_off[base + t] = excl;
            g_cur[base + t] = excl;
        }
        __syncthreads();
        if (t == 1023) s_carry = carry + incl;
        __syncthreads();
    }
    if (t == 0) g_off[NN] = E;
}

__global__ void k_fill(const int* __restrict__ src, const int* __restrict__ dst, int E) {
    int e = blockIdx.x * blockDim.x + threadIdx.x;
    if (e < E) {
        int p = atomicAdd(&g_cur[dst[e]], 1);
        g_col[p] = src[e];
    }
}

// ---------------- aggregation: one warp per dst; half gather, fp32 accum ------
template <int D, int SEL>
__global__ void k_agg() {
    const __half* X   = (SEL == 0) ? g_xh  : g_h1h;
    __half*       OUT = (SEL == 0) ? g_m1h : g_m2h;

    int gw   = (blockIdx.x * blockDim.x + threadIdx.x) >> 5;
    int lane = threadIdx.x & 31;
    if (gw >= NN) return;

    constexpr int V = D / 64;   // half2 per lane
    float2 acc[V];
#pragma unroll
    for (int v = 0; v < V; v++) acc[v] = make_float2(0.f, 0.f);

    int s0 = g_off[gw], s1 = g_off[gw + 1];
    for (int i = s0; i < s1; i += 32) {
        int cnt = min(32, s1 - i);
        int my  = (lane < cnt) ? g_col[i + lane] : 0;
        int j = 0;
        for (; j + 4 <= cnt; j += 4) {
            int i0 = __shfl_sync(0xffffffffu, my, j + 0);
            int i1 = __shfl_sync(0xffffffffu, my, j + 1);
            int i2 = __shfl_sync(0xffffffffu, my, j + 2);
            int i3 = __shfl_sync(0xffffffffu, my, j + 3);
            const uint32_t* p0 = (const uint32_t*)(X + (size_t)i0 * D);
            const uint32_t* p1 = (const uint32_t*)(X + (size_t)i1 * D);
            const uint32_t* p2 = (const uint32_t*)(X + (size_t)i2 * D);
            const uint32_t* p3 = (const uint32_t*)(X + (size_t)i3 * D);
#pragma unroll
            for (int v = 0; v < V; v++) {
                uint32_t u0 = p0[v * 32 + lane];
                uint32_t u1 = p1[v * 32 + lane];
                uint32_t u2 = p2[v * 32 + lane];
                uint32_t u3 = p3[v * 32 + lane];
                float2 f0 = __half22float2(*(__half2*)&u0);
                float2 f1 = __half22float2(*(__half2*)&u1);
                float2 f2 = __half22float2(*(__half2*)&u2);
                float2 f3 = __half22float2(*(__half2*)&u3);
                acc[v].x += f0.x + f1.x + f2.x + f3.x;
                acc[v].y += f0.y + f1.y + f2.y + f3.y;
            }
        }
        for (; j < cnt; j++) {
            int sidx = __shfl_sync(0xffffffffu, my, j);
            const uint32_t* p = (const uint32_t*)(X + (size_t)sidx * D);
#pragma unroll
            for (int v = 0; v < V; v++) {
                uint32_t u = p[v * 32 + lane];
                float2 f = __half22float2(*(__half2*)&u);
                acc[v].x += f.x;
                acc[v].y += f.y;
            }
        }
    }
    int deg = s1 - s0;
    float inv = 1.0f / (float)max(deg, 1);
    uint32_t* orow = (uint32_t*)(OUT + (size_t)gw * D);
#pragma unroll
    for (int v = 0; v < V; v++) {
        __half2 h = __floats2half2_rn(acc[v].x * inv, acc[v].y * inv);
        orow[v * 32 + lane] = *(uint32_t*)&h;
    }
}

// ---------------- fp16 mma.sync fused two-input GEMM + bias + ReLU ---------------
// C = relu(A1@W1^T + A2@W2^T + bias), all operands fp16, accum fp32.
// BM=128, BN=128, BK=32 halves; 8 warps 2x4; warp tile 64x32 via m16n8k16.
#define PADH 40                              // halves per smem row (80 B)
#define TILE_BYTES (128 * PADH * 2)          // 10240
#define STAGE_BYTES (2 * TILE_BYTES)         // 20480 (A + W)
#define STAGE_HALVES (STAGE_BYTES / 2)

template <int K, int SEL>
__device__ __forceinline__ void load_chunk(int c, int m0, int n0, uint32_t sb, int tid) {
    constexpr int NCH = (2 * K) / 32;
    const __half* A1 = (SEL == 0) ? g_m1h  : g_m2h;
    const __half* A2 = (SEL == 0) ? g_xh   : g_h1h;
    const __half* W1 = (SEL == 0) ? g_w1lh : g_w2lh;
    const __half* W2 = (SEL == 0) ? g_w1rh : g_w2rh;

    int st = c & 1;
    int ss = (c >= NCH / 2);
    int k0 = (c - ss * (NCH / 2)) * 32;
    const __half* A = ss ? A2 : A1;
    const __half* W = ss ? W2 : W1;

    int row = tid >> 1;          // 0..127
    int q   = (tid & 1) * 2;     // 16B-chunk 0 or 2

    uint32_t base = sb + (uint32_t)st * STAGE_BYTES;
    uint32_t adst = base + row * (PADH * 2) + q * 16;
    uint32_t wdst = adst + TILE_BYTES;

    int  arow = m0 + row;
    bool v    = (arow < NN);
    int  ar   = v ? arow : 0;
    const __half* asrc = A + (size_t)ar * K + k0 + q * 8;
    const __half* wsrc = W + (size_t)(n0 + row) * K + k0 + q * 8;
    cp16(adst,      asrc,     v);
    cp16(adst + 16, asrc + 8, v);
    cp16(wdst,      wsrc,     true);
    cp16(wdst + 16, wsrc + 8, true);
    asm volatile("cp.async.commit_group;" ::: "memory");
}

template <int K, int SEL>
__global__ void __launch_bounds__(256) k_gemm_h(const float* __restrict__ bias) {
    __half* C = (SEL == 0) ? g_h1h : g_h2h;
    constexpr int NCH = (2 * K) / 32;

    __shared__ __align__(16) __half smem[2 * STAGE_HALVES];
    uint32_t sb = smem_u32(smem);

    const int tid  = threadIdx.x;
    const int warp = tid >> 5;
    const int lane = tid & 31;
    const int g    = lane >> 2;
    const int t    = lane & 3;
    const int m0   = blockIdx.x * 128;
    const int n0   = blockIdx.y * 128;
    const int wm   = warp >> 2;   // 0..1
    const int wn   = warp & 3;    // 0..3

    float acc[4][4][4];
#pragma unroll
    for (int i = 0; i < 4; i++)
#pragma unroll
        for (int j = 0; j < 4; j++)
#pragma unroll
            for (int c = 0; c < 4; c++) acc[i][j][c] = 0.f;

    load_chunk<K, SEL>(0, m0, n0, sb, tid);

    for (int c = 0; c < NCH; c++) {
        if (c + 1 < NCH) {
            load_chunk<K, SEL>(c + 1, m0, n0, sb, tid);
            asm volatile("cp.async.wait_group 1;" ::: "memory");
        } else {
            asm volatile("cp.async.wait_group 0;" ::: "memory");
        }
        __syncthreads();

        const __half* As = smem + (c & 1) * STAGE_HALVES;
        const __half* Ws = As + 128 * PADH;

#pragma unroll
        for (int ks = 0; ks < 2; ks++) {
            const int kb = ks * 16 + 2 * t;
            uint32_t b[4][2];
#pragma unroll
            for (int nt = 0; nt < 4; nt++) {
                int col = wn * 32 + nt * 8 + g;
                b[nt][0] = *(const uint32_t*)(Ws + col * PADH + kb);
                b[nt][1] = *(const uint32_t*)(Ws + col * PADH + kb + 8);
            }
#pragma unroll
            for (int mt = 0; mt < 4; mt++) {
                int r = wm * 64 + mt * 16 + g;
                uint32_t a[4];
                a[0] = *(const uint32_t*)(As + r * PADH + kb);
                a[1] = *(const uint32_t*)(As + (r + 8) * PADH + kb);
                a[2] = *(const uint32_t*)(As + r * PADH + kb + 8);
                a[3] = *(const uint32_t*)(As + (r + 8) * PADH + kb + 8);
#pragma unroll
                for (int nt = 0; nt < 4; nt++)
                    mma_f16(acc[mt][nt], a, b[nt]);
            }
        }
        __syncthreads();
    }

    // epilogue: bias + relu -> half2 stores
#pragma unroll
    for (int mt = 0; mt < 4; mt++) {
#pragma unroll
        for (int nt = 0; nt < 4; nt++) {
            int col = n0 + wn * 32 + nt * 8 + 2 * t;
            float b0 = bias[col], b1 = bias[col + 1];
            int r0 = m0 + wm * 64 + mt * 16 + g;
            if (r0 < NN) {
                __half2 h = __floats2half2_rn(fmaxf(acc[mt][nt][0] + b0, 0.f),
                                              fmaxf(acc[mt][nt][1] + b1, 0.f));
                *(uint32_t*)(C + (size_t)r0 * DH + col) = *(uint32_t*)&h;
            }
            int r1 = r0 + 8;
            if (r1 < NN) {
                __half2 h = __floats2half2_rn(fmaxf(acc[mt][nt][2] + b0, 0.f),
                                              fmaxf(acc[mt][nt][3] + b1, 0.f));
                *(uint32_t*)(C + (size_t)r1 * DH + col) = *(uint32_t*)&h;
            }
        }
    }
}

// ---------------- head: out[n] = dot(h2[n,:], head_w) + head_b ----------------
__global__ void k_head(const float* __restrict__ HW, const float* __restrict__ HB,
                       float* __restrict__ out) {
    int gw   = (blockIdx.x * blockDim.x + threadIdx.x) >> 5;
    int lane = threadIdx.x & 31;
    if (gw >= NN) return;
    const uint32_t* h = (const uint32_t*)(g_h2h + (size_t)gw * 256);
    float s = 0.f;
#pragma unroll
    for (int v = 0; v < 4; v++) {
        uint32_t u = h[v * 32 + lane];
        float2 f = __half22float2(*(__half2*)&u);
        int idx = (v * 32 + lane) * 2;
        s += f.x * HW[idx] + f.y * HW[idx + 1];
    }
#pragma unroll
    for (int o = 16; o; o >>= 1) s += __shfl_xor_sync(0xffffffffu, s, o);
    if (lane == 0) out[gw] = s + HB[0];
}

// ---------------- launch ----------------
extern "C" void kernel_launch(void* const* d_in, const int* in_sizes, int n_in,
                              void* d_out, int out_size) {
    const float* x   = (const float*)d_in[0];
    const int*   ei  = (const int*)d_in[1];
    const float* W1l = (const float*)d_in[2];
    const float* b1  = (const float*)d_in[3];
    const float* W1r = (const float*)d_in[4];
    const float* W2l = (const float*)d_in[5];
    const float* b2  = (const float*)d_in[6];
    const float* W2r = (const float*)d_in[7];
    const float* hw  = (const float*)d_in[8];
    const float* hb  = (const float*)d_in[9];
    float* out = (float*)d_out;

    int E = in_sizes[1] / 2;
    const int* srcp = ei;
    const int* dstp = ei + E;

    // fp16 conversion (+ deg zeroing folded into k_round_x)
    k_round_x<<<(NN * 128 / 4 + 255) / 256, 256>>>(x);
    k_round_w<<<(256 * 256 + 255) / 256, 256>>>(W1l, W1r, W2l, W2r);

    // CSR build
    k_count<<<(E + 255) / 256, 256>>>(dstp, E);
    k_scan<<<1, 1024>>>(E);
    k_fill<<<(E + 255) / 256, 256>>>(srcp, dstp, E);

    dim3 gemm_grid((NN + 127) / 128, 2);
    int  agg_blocks = (NN * 32 + 255) / 256;

    // Layer 1
    k_agg<128, 0><<<agg_blocks, 256>>>();
    k_gemm_h<128, 0><<<gemm_grid, 256>>>(b1);

    // Layer 2
    k_agg<256, 1><<<agg_blocks, 256>>>();
    k_gemm_h<256, 1><<<gemm_grid, 256>>>(b2);

    // Head
    k_head<<<agg_blocks, 256>>>(hw, hb, out);
}

// round 7
// speedup vs baseline: 3.1591x; 1.1286x over previous
#include <cuda_runtime.h>
#include <cuda_fp16.h>
#include <cstdint>

#define NN   50000
#define EMAX 800000
#define DH   256
#define SCAN_B 1024
#define NBLK ((NN + SCAN_B - 1) / SCAN_B)   // 49

// ---------------- scratch (device globals; allocation-free) ----------------
__device__ __align__(16) int    g_deg[NN];
__device__ __align__(16) int    g_off[NN + 1];
__device__ __align__(16) int    g_cur[NN];
__device__ __align__(16) int    g_part[NBLK];
__device__ __align__(16) int    g_col[EMAX];
__device__ __align__(16) __half g_xh  [(size_t)NN * 128];   // x in fp16
__device__ __align__(16) __half g_w1lh[256 * 128];
__device__ __align__(16) __half g_w1rh[256 * 128];
__device__ __align__(16) __half g_w2lh[256 * 256];
__device__ __align__(16) __half g_w2rh[256 * 256];
__device__ __align__(16) __half g_m1h [(size_t)NN * 128];
__device__ __align__(16) __half g_h1h [(size_t)NN * 256];
__device__ __align__(16) __half g_m2h [(size_t)NN * 256];
__device__ __align__(16) __half g_h2h [(size_t)NN * 256];

// ---------------- helpers ----------------
__device__ __forceinline__ uint32_t smem_u32(const void* p) {
    uint32_t a;
    asm("{ .reg .u64 t; cvta.to.shared.u64 t, %1; cvt.u32.u64 %0, t; }" : "=r"(a) : "l"(p));
    return a;
}

__device__ __forceinline__ void cp16(uint32_t dst, const void* src, bool v) {
    int sz = v ? 16 : 0;
    asm volatile("cp.async.cg.shared.global [%0], [%1], 16, %2;\n"
                 :: "r"(dst), "l"(src), "r"(sz) : "memory");
}

__device__ __forceinline__ void mma_f16(float c[4], const uint32_t a[4], const uint32_t b[2]) {
    asm volatile(
        "mma.sync.aligned.m16n8k16.row.col.f32.f16.f16.f32 "
        "{%0,%1,%2,%3}, {%4,%5,%6,%7}, {%8,%9}, {%0,%1,%2,%3};\n"
        : "+f"(c[0]), "+f"(c[1]), "+f"(c[2]), "+f"(c[3])
        : "r"(a[0]), "r"(a[1]), "r"(a[2]), "r"(a[3]), "r"(b[0]), "r"(b[1]));
}

__device__ __forceinline__ int warp_iscan(int x, int lane) {
#pragma unroll
    for (int o = 1; o < 32; o <<= 1) {
        int y = __shfl_up_sync(0xffffffffu, x, o);
        if (lane >= o) x += y;
    }
    return x;
}

// ---------------- conversion kernels ----------------
__global__ void k_round_x(const float* __restrict__ x) {
    int i = blockIdx.x * blockDim.x + threadIdx.x;
    if (i < NN) g_deg[i] = 0;                 // fold CSR zeroing in here
    if (i < NN * 128 / 4) {
        float4 v = ((const float4*)x)[i];
        __half2 h0 = __floats2half2_rn(v.x, v.y);
        __half2 h1 = __floats2half2_rn(v.z, v.w);
        uint2 o;
        o.x = *(uint32_t*)&h0;
        o.y = *(uint32_t*)&h1;
        ((uint2*)g_xh)[i] = o;
    }
}

__global__ void k_round_w(const float* __restrict__ W1l, const float* __restrict__ W1r,
                          const float* __restrict__ W2l, const float* __restrict__ W2r) {
    int i = blockIdx.x * blockDim.x + threadIdx.x;
    if (i < 256 * 128) {
        g_w1lh[i] = __float2half_rn(W1l[i]);
        g_w1rh[i] = __float2half_rn(W1r[i]);
    }
    if (i < 256 * 256) {
        g_w2lh[i] = __float2half_rn(W2l[i]);
        g_w2rh[i] = __float2half_rn(W2r[i]);
    }
}

// ---------------- CSR build ----------------
__global__ void k_count(const int* __restrict__ dst, int E) {
    int e = blockIdx.x * blockDim.x + threadIdx.x;
    if (e < E) atomicAdd(&g_deg[dst[e]], 1);
}

// multi-block scan, phase 1: per-block exclusive scan + block sums
__global__ void k_scan1() {
    __shared__ int wsum[32];
    int t = threadIdx.x, lane = t & 31, w = t >> 5;
    int i = blockIdx.x * SCAN_B + t;
    int v = (i < NN) ? g_deg[i] : 0;
    int x = warp_iscan(v, lane);
    if (lane == 31) wsum[w] = x;
    __syncthreads();
    if (w == 0) {
        int y = wsum[lane];
        int z = warp_iscan(y, lane);
        wsum[lane] = z - y;   // exclusive warp offsets
    }
    __syncthreads();
    int incl = x + wsum[w];
    if (i < NN) g_off[i] = incl - v;          // local exclusive
    if (t == SCAN_B - 1) g_part[blockIdx.x] = incl;  // block total
}

// phase 2: scan the 49 block sums (single warp-sized pass, 2 warps)
__global__ void k_scan2() {
    __shared__ int wtot[2];
    int t = threadIdx.x, lane = t & 31, w = t >> 5;
    int v = (t < NBLK) ? g_part[t] : 0;
    int x = warp_iscan(v, lane);
    if (lane == 31) wtot[w] = x;
    __syncthreads();
    int off = (w == 1) ? wtot[0] : 0;
    if (t < NBLK) g_part[t] = x - v + off;    // exclusive block offsets
}

// phase 3: add block offsets, produce g_cur and sentinel
__global__ void k_scan3(int E) {
    int i = blockIdx.x * SCAN_B + threadIdx.x;
    if (i < NN) {
        int e = g_off[i] + g_part[blockIdx.x];
        g_off[i] = e;
        g_cur[i] = e;
    }
    if (i == 0) g_off[NN] = E;
}

__global__ void k_fill(const int* __restrict__ src, const int* __restrict__ dst, int E) {
    int e = blockIdx.x * blockDim.x + threadIdx.x;
    if (e < E) {
        int p = atomicAdd(&g_cur[dst[e]], 1);
        g_col[p] = src[e];
    }
}

// ---------------- aggregation: one warp per dst; half gather, fp32 accum ------
template <int D, int SEL>
__global__ void k_agg() {
    const __half* X   = (SEL == 0) ? g_xh  : g_h1h;
    __half*       OUT = (SEL == 0) ? g_m1h : g_m2h;

    int gw   = (blockIdx.x * blockDim.x + threadIdx.x) >> 5;
    int lane = threadIdx.x & 31;
    if (gw >= NN) return;

    constexpr int V = D / 64;   // half2 per lane
    float2 acc[V];
#pragma unroll
    for (int v = 0; v < V; v++) acc[v] = make_float2(0.f, 0.f);

    int s0 = g_off[gw], s1 = g_off[gw + 1];
    for (int i = s0; i < s1; i += 32) {
        int cnt = min(32, s1 - i);
        int my  = (lane < cnt) ? g_col[i + lane] : 0;
        int j = 0;
        for (; j + 4 <= cnt; j += 4) {
            int i0 = __shfl_sync(0xffffffffu, my, j + 0);
            int i1 = __shfl_sync(0xffffffffu, my, j + 1);
            int i2 = __shfl_sync(0xffffffffu, my, j + 2);
            int i3 = __shfl_sync(0xffffffffu, my, j + 3);
            const uint32_t* p0 = (const uint32_t*)(X + (size_t)i0 * D);
            const uint32_t* p1 = (const uint32_t*)(X + (size_t)i1 * D);
            const uint32_t* p2 = (const uint32_t*)(X + (size_t)i2 * D);
            const uint32_t* p3 = (const uint32_t*)(X + (size_t)i3 * D);
#pragma unroll
            for (int v = 0; v < V; v++) {
                uint32_t u0 = p0[v * 32 + lane];
                uint32_t u1 = p1[v * 32 + lane];
                uint32_t u2 = p2[v * 32 + lane];
                uint32_t u3 = p3[v * 32 + lane];
                float2 f0 = __half22float2(*(__half2*)&u0);
                float2 f1 = __half22float2(*(__half2*)&u1);
                float2 f2 = __half22float2(*(__half2*)&u2);
                float2 f3 = __half22float2(*(__half2*)&u3);
                acc[v].x += f0.x + f1.x + f2.x + f3.x;
                acc[v].y += f0.y + f1.y + f2.y + f3.y;
            }
        }
        for (; j < cnt; j++) {
            int sidx = __shfl_sync(0xffffffffu, my, j);
            const uint32_t* p = (const uint32_t*)(X + (size_t)sidx * D);
#pragma unroll
            for (int v = 0; v < V; v++) {
                uint32_t u = p[v * 32 + lane];
                float2 f = __half22float2(*(__half2*)&u);
                acc[v].x += f.x;
                acc[v].y += f.y;
            }
        }
    }
    int deg = s1 - s0;
    float inv = 1.0f / (float)max(deg, 1);
    uint32_t* orow = (uint32_t*)(OUT + (size_t)gw * D);
#pragma unroll
    for (int v = 0; v < V; v++) {
        __half2 h = __floats2half2_rn(acc[v].x * inv, acc[v].y * inv);
        orow[v * 32 + lane] = *(uint32_t*)&h;
    }
}

// ---------------- fp16 mma.sync fused two-input GEMM + bias + ReLU ---------------
// C = relu(A1@W1^T + A2@W2^T + bias), all operands fp16, accum fp32.
// BM=128, BN=128, BK=32 halves; 8 warps 2x4; warp tile 64x32 via m16n8k16.
#define PADH 40                              // halves per smem row (80 B)
#define TILE_BYTES (128 * PADH * 2)          // 10240
#define STAGE_BYTES (2 * TILE_BYTES)         // 20480 (A + W)
#define STAGE_HALVES (STAGE_BYTES / 2)

template <int K, int SEL>
__device__ __forceinline__ void load_chunk(int c, int m0, int n0, uint32_t sb, int tid) {
    constexpr int NCH = (2 * K) / 32;
    const __half* A1 = (SEL == 0) ? g_m1h  : g_m2h;
    const __half* A2 = (SEL == 0) ? g_xh   : g_h1h;
    const __half* W1 = (SEL == 0) ? g_w1lh : g_w2lh;
    const __half* W2 = (SEL == 0) ? g_w1rh : g_w2rh;

    int st = c & 1;
    int ss = (c >= NCH / 2);
    int k0 = (c - ss * (NCH / 2)) * 32;
    const __half* A = ss ? A2 : A1;
    const __half* W = ss ? W2 : W1;

    int row = tid >> 1;          // 0..127
    int q   = (tid & 1) * 2;     // 16B-chunk 0 or 2

    uint32_t base = sb + (uint32_t)st * STAGE_BYTES;
    uint32_t adst = base + row * (PADH * 2) + q * 16;
    uint32_t wdst = adst + TILE_BYTES;

    int  arow = m0 + row;
    bool v    = (arow < NN);
    int  ar   = v ? arow : 0;
    const __half* asrc = A + (size_t)ar * K + k0 + q * 8;
    const __half* wsrc = W + (size_t)(n0 + row) * K + k0 + q * 8;
    cp16(adst,      asrc,     v);
    cp16(adst + 16, asrc + 8, v);
    cp16(wdst,      wsrc,     true);
    cp16(wdst + 16, wsrc + 8, true);
    asm volatile("cp.async.commit_group;" ::: "memory");
}

template <int K, int SEL>
__global__ void __launch_bounds__(256) k_gemm_h(const float* __restrict__ bias) {
    __half* C = (SEL == 0) ? g_h1h : g_h2h;
    constexpr int NCH = (2 * K) / 32;

    __shared__ __align__(16) __half smem[2 * STAGE_HALVES];
    uint32_t sb = smem_u32(smem);

    const int tid  = threadIdx.x;
    const int warp = tid >> 5;
    const int lane = tid & 31;
    const int g    = lane >> 2;
    const int t    = lane & 3;
    const int m0   = blockIdx.x * 128;
    const int n0   = blockIdx.y * 128;
    const int wm   = warp >> 2;   // 0..1
    const int wn   = warp & 3;    // 0..3

    float acc[4][4][4];
#pragma unroll
    for (int i = 0; i < 4; i++)
#pragma unroll
        for (int j = 0; j < 4; j++)
#pragma unroll
            for (int c = 0; c < 4; c++) acc[i][j][c] = 0.f;

    load_chunk<K, SEL>(0, m0, n0, sb, tid);

    for (int c = 0; c < NCH; c++) {
        if (c + 1 < NCH) {
            load_chunk<K, SEL>(c + 1, m0, n0, sb, tid);
            asm volatile("cp.async.wait_group 1;" ::: "memory");
        } else {
            asm volatile("cp.async.wait_group 0;" ::: "memory");
        }
        __syncthreads();

        const __half* As = smem + (c & 1) * STAGE_HALVES;
        const __half* Ws = As + 128 * PADH;

#pragma unroll
        for (int ks = 0; ks < 2; ks++) {
            const int kb = ks * 16 + 2 * t;
            uint32_t b[4][2];
#pragma unroll
            for (int nt = 0; nt < 4; nt++) {
                int col = wn * 32 + nt * 8 + g;
                b[nt][0] = *(const uint32_t*)(Ws + col * PADH + kb);
                b[nt][1] = *(const uint32_t*)(Ws + col * PADH + kb + 8);
            }
#pragma unroll
            for (int mt = 0; mt < 4; mt++) {
                int r = wm * 64 + mt * 16 + g;
                uint32_t a[4];
                a[0] = *(const uint32_t*)(As + r * PADH + kb);
                a[1] = *(const uint32_t*)(As + (r + 8) * PADH + kb);
                a[2] = *(const uint32_t*)(As + r * PADH + kb + 8);
                a[3] = *(const uint32_t*)(As + (r + 8) * PADH + kb + 8);
#pragma unroll
                for (int nt = 0; nt < 4; nt++)
                    mma_f16(acc[mt][nt], a, b[nt]);
            }
        }
        __syncthreads();
    }

    // epilogue: bias + relu -> half2 stores
#pragma unroll
    for (int mt = 0; mt < 4; mt++) {
#pragma unroll
        for (int nt = 0; nt < 4; nt++) {
            int col = n0 + wn * 32 + nt * 8 + 2 * t;
            float b0 = bias[col], b1 = bias[col + 1];
            int r0 = m0 + wm * 64 + mt * 16 + g;
            if (r0 < NN) {
                __half2 h = __floats2half2_rn(fmaxf(acc[mt][nt][0] + b0, 0.f),
                                              fmaxf(acc[mt][nt][1] + b1, 0.f));
                *(uint32_t*)(C + (size_t)r0 * DH + col) = *(uint32_t*)&h;
            }
            int r1 = r0 + 8;
            if (r1 < NN) {
                __half2 h = __floats2half2_rn(fmaxf(acc[mt][nt][2] + b0, 0.f),
                                              fmaxf(acc[mt][nt][3] + b1, 0.f));
                *(uint32_t*)(C + (size_t)r1 * DH + col) = *(uint32_t*)&h;
            }
        }
    }
}

// ---------------- head: out[n] = dot(h2[n,:], head_w) + head_b ----------------
__global__ void k_head(const float* __restrict__ HW, const float* __restrict__ HB,
                       float* __restrict__ out) {
    int gw   = (blockIdx.x * blockDim.x + threadIdx.x) >> 5;
    int lane = threadIdx.x & 31;
    if (gw >= NN) return;
    const uint32_t* h = (const uint32_t*)(g_h2h + (size_t)gw * 256);
    float s = 0.f;
#pragma unroll
    for (int v = 0; v < 4; v++) {
        uint32_t u = h[v * 32 + lane];
        float2 f = __half22float2(*(__half2*)&u);
        int idx = (v * 32 + lane) * 2;
        s += f.x * HW[idx] + f.y * HW[idx + 1];
    }
#pragma unroll
    for (int o = 16; o; o >>= 1) s += __shfl_xor_sync(0xffffffffu, s, o);
    if (lane == 0) out[gw] = s + HB[0];
}

// ---------------- launch ----------------
extern "C" void kernel_launch(void* const* d_in, const int* in_sizes, int n_in,
                              void* d_out, int out_size) {
    const float* x   = (const float*)d_in[0];
    const int*   ei  = (const int*)d_in[1];
    const float* W1l = (const float*)d_in[2];
    const float* b1  = (const float*)d_in[3];
    const float* W1r = (const float*)d_in[4];
    const float* W2l = (const float*)d_in[5];
    const float* b2  = (const float*)d_in[6];
    const float* W2r = (const float*)d_in[7];
    const float* hw  = (const float*)d_in[8];
    const float* hb  = (const float*)d_in[9];
    float* out = (float*)d_out;

    int E = in_sizes[1] / 2;
    const int* srcp = ei;
    const int* dstp = ei + E;

    // fp16 conversion (+ deg zeroing folded into k_round_x)
    k_round_x<<<(NN * 128 / 4 + 255) / 256, 256>>>(x);
    k_round_w<<<(256 * 256 + 255) / 256, 256>>>(W1l, W1r, W2l, W2r);

    // CSR build (parallel 3-phase scan)
    k_count<<<(E + 255) / 256, 256>>>(dstp, E);
    k_scan1<<<NBLK, SCAN_B>>>();
    k_scan2<<<1, 64>>>();
    k_scan3<<<NBLK, SCAN_B>>>(E);
    k_fill<<<(E + 255) / 256, 256>>>(srcp, dstp, E);

    dim3 gemm_grid((NN + 127) / 128, 2);
    int  agg_blocks = (NN * 32 + 255) / 256;

    // Layer 1
    k_agg<128, 0><<<agg_blocks, 256>>>();
    k_gemm_h<128, 0><<<gemm_grid, 256>>>(b1);

    // Layer 2
    k_agg<256, 1><<<agg_blocks, 256>>>();
    k_gemm_h<256, 1><<<gemm_grid, 256>>>(b2);

    // Head
    k_head<<<agg_blocks, 256>>>(hw, hb, out);
}

// round 8
// speedup vs baseline: 3.3859x; 1.0718x over previous
#include <cuda_runtime.h>
#include <cuda_fp16.h>
#include <cstdint>

#define NN   50000
#define EMAX 800000
#define DH   256
#define SCAN_B 1024
#define NBLK ((NN + SCAN_B - 1) / SCAN_B)   // 49

// ---------------- scratch (device globals; allocation-free) ----------------
__device__ __align__(16) int    g_deg[NN];
__device__ __align__(16) int    g_off[NN + 1];
__device__ __align__(16) int    g_cur[NN];
__device__ __align__(16) int    g_part[NBLK];
__device__ __align__(16) int    g_col[EMAX];
__device__ __align__(16) __half g_xh  [(size_t)NN * 128];   // x in fp16
__device__ __align__(16) __half g_w1lh[256 * 128];
__device__ __align__(16) __half g_w1rh[256 * 128];
__device__ __align__(16) __half g_w2lh[256 * 256];
__device__ __align__(16) __half g_w2rh[256 * 256];
__device__ __align__(16) __half g_m1h [(size_t)NN * 128];
__device__ __align__(16) __half g_h1h [(size_t)NN * 256];
__device__ __align__(16) __half g_m2h [(size_t)NN * 256];
__device__ __align__(16) __half g_h2h [(size_t)NN * 256];

// ---------------- helpers ----------------
__device__ __forceinline__ uint32_t smem_u32(const void* p) {
    uint32_t a;
    asm("{ .reg .u64 t; cvta.to.shared.u64 t, %1; cvt.u32.u64 %0, t; }" : "=r"(a) : "l"(p));
    return a;
}

__device__ __forceinline__ void cp16(uint32_t dst, const void* src, bool v) {
    int sz = v ? 16 : 0;
    asm volatile("cp.async.cg.shared.global [%0], [%1], 16, %2;\n"
                 :: "r"(dst), "l"(src), "r"(sz) : "memory");
}

__device__ __forceinline__ void mma_f16(float c[4], const uint32_t a[4], const uint32_t b[2]) {
    asm volatile(
        "mma.sync.aligned.m16n8k16.row.col.f32.f16.f16.f32 "
        "{%0,%1,%2,%3}, {%4,%5,%6,%7}, {%8,%9}, {%0,%1,%2,%3};\n"
        : "+f"(c[0]), "+f"(c[1]), "+f"(c[2]), "+f"(c[3])
        : "r"(a[0]), "r"(a[1]), "r"(a[2]), "r"(a[3]), "r"(b[0]), "r"(b[1]));
}

__device__ __forceinline__ void ldsm_x4(uint32_t r[4], uint32_t addr) {
    asm volatile("ldmatrix.sync.aligned.m8n8.x4.shared.b16 {%0,%1,%2,%3}, [%4];"
                 : "=r"(r[0]), "=r"(r[1]), "=r"(r[2]), "=r"(r[3]) : "r"(addr));
}

__device__ __forceinline__ void ldsm_x2(uint32_t& r0, uint32_t& r1, uint32_t addr) {
    asm volatile("ldmatrix.sync.aligned.m8n8.x2.shared.b16 {%0,%1}, [%2];"
                 : "=r"(r0), "=r"(r1) : "r"(addr));
}

__device__ __forceinline__ int warp_iscan(int x, int lane) {
#pragma unroll
    for (int o = 1; o < 32; o <<= 1) {
        int y = __shfl_up_sync(0xffffffffu, x, o);
        if (lane >= o) x += y;
    }
    return x;
}

// ---------------- conversion kernels ----------------
__global__ void k_round_x(const float* __restrict__ x) {
    int i = blockIdx.x * blockDim.x + threadIdx.x;
    if (i < NN) g_deg[i] = 0;                 // zero deg BEFORE k_prep's atomics
    if (i < NN * 128 / 4) {
        float4 v = ((const float4*)x)[i];
        __half2 h0 = __floats2half2_rn(v.x, v.y);
        __half2 h1 = __floats2half2_rn(v.z, v.w);
        uint2 o;
        o.x = *(uint32_t*)&h0;
        o.y = *(uint32_t*)&h1;
        ((uint2*)g_xh)[i] = o;
    }
}

// weight conversion + edge degree count, fused (runs after k_round_x)
__global__ void k_prep(const float* __restrict__ W1l, const float* __restrict__ W1r,
                       const float* __restrict__ W2l, const float* __restrict__ W2r,
                       const int* __restrict__ dst, int E) {
    int i = blockIdx.x * blockDim.x + threadIdx.x;
    if (i < 256 * 128) {
        g_w1lh[i] = __float2half_rn(W1l[i]);
        g_w1rh[i] = __float2half_rn(W1r[i]);
    }
    if (i < 256 * 256) {
        g_w2lh[i] = __float2half_rn(W2l[i]);
        g_w2rh[i] = __float2half_rn(W2r[i]);
    }
    if (i < E) atomicAdd(&g_deg[dst[i]], 1);
}

// ---------------- CSR build: 3-phase scan ----------------
__global__ void k_scan1() {
    __shared__ int wsum[32];
    int t = threadIdx.x, lane = t & 31, w = t >> 5;
    int i = blockIdx.x * SCAN_B + t;
    int v = (i < NN) ? g_deg[i] : 0;
    int x = warp_iscan(v, lane);
    if (lane == 31) wsum[w] = x;
    __syncthreads();
    if (w == 0) {
        int y = wsum[lane];
        int z = warp_iscan(y, lane);
        wsum[lane] = z - y;
    }
    __syncthreads();
    int incl = x + wsum[w];
    if (i < NN) g_off[i] = incl - v;
    if (t == SCAN_B - 1) g_part[blockIdx.x] = incl;
}

__global__ void k_scan2() {
    __shared__ int wtot[2];
    int t = threadIdx.x, lane = t & 31, w = t >> 5;
    int v = (t < NBLK) ? g_part[t] : 0;
    int x = warp_iscan(v, lane);
    if (lane == 31) wtot[w] = x;
    __syncthreads();
    int off = (w == 1) ? wtot[0] : 0;
    if (t < NBLK) g_part[t] = x - v + off;
}

__global__ void k_scan3(int E) {
    int i = blockIdx.x * SCAN_B + threadIdx.x;
    if (i < NN) {
        int e = g_off[i] + g_part[blockIdx.x];
        g_off[i] = e;
        g_cur[i] = e;
    }
    if (i == 0) g_off[NN] = E;
}

__global__ void k_fill(const int* __restrict__ src, const int* __restrict__ dst, int E) {
    int e = blockIdx.x * blockDim.x + threadIdx.x;
    if (e < E) {
        int p = atomicAdd(&g_cur[dst[e]], 1);
        g_col[p] = src[e];
    }
}

// ---------------- aggregation: one warp per dst; uint2 gathers, fp32 accum ----
template <int D, int SEL>
__global__ void k_agg() {
    const __half* X   = (SEL == 0) ? g_xh  : g_h1h;
    __half*       OUT = (SEL == 0) ? g_m1h : g_m2h;

    int gw   = (blockIdx.x * blockDim.x + threadIdx.x) >> 5;
    int lane = threadIdx.x & 31;
    if (gw >= NN) return;

    constexpr int V2    = D / 128;             // uint2 (4 halves) per lane
    constexpr int BATCH = (D == 128) ? 8 : 4;  // neighbors per inner step
    float acc[V2][4];
#pragma unroll
    for (int v = 0; v < V2; v++)
#pragma unroll
        for (int q = 0; q < 4; q++) acc[v][q] = 0.f;

    int s0 = g_off[gw], s1 = g_off[gw + 1];
    for (int i = s0; i < s1; i += 32) {
        int cnt = min(32, s1 - i);
        int my  = (lane < cnt) ? g_col[i + lane] : 0;
        int j = 0;
        for (; j + BATCH <= cnt; j += BATCH) {
            const uint2* p[BATCH];
#pragma unroll
            for (int b = 0; b < BATCH; b++) {
                int s = __shfl_sync(0xffffffffu, my, j + b);
                p[b] = (const uint2*)(X + (size_t)s * D);
            }
            uint2 u[BATCH][V2];
#pragma unroll
            for (int b = 0; b < BATCH; b++)
#pragma unroll
                for (int v = 0; v < V2; v++) u[b][v] = p[b][v * 32 + lane];
#pragma unroll
            for (int b = 0; b < BATCH; b++)
#pragma unroll
                for (int v = 0; v < V2; v++) {
                    float2 f0 = __half22float2(*(__half2*)&u[b][v].x);
                    float2 f1 = __half22float2(*(__half2*)&u[b][v].y);
                    acc[v][0] += f0.x; acc[v][1] += f0.y;
                    acc[v][2] += f1.x; acc[v][3] += f1.y;
                }
        }
        for (; j < cnt; j++) {
            int s = __shfl_sync(0xffffffffu, my, j);
            const uint2* p = (const uint2*)(X + (size_t)s * D);
#pragma unroll
            for (int v = 0; v < V2; v++) {
                uint2 u = p[v * 32 + lane];
                float2 f0 = __half22float2(*(__half2*)&u.x);
                float2 f1 = __half22float2(*(__half2*)&u.y);
                acc[v][0] += f0.x; acc[v][1] += f0.y;
                acc[v][2] += f1.x; acc[v][3] += f1.y;
            }
        }
    }
    int deg = s1 - s0;
    float inv = 1.0f / (float)max(deg, 1);
    uint2* orow = (uint2*)(OUT + (size_t)gw * D);
#pragma unroll
    for (int v = 0; v < V2; v++) {
        __half2 h0 = __floats2half2_rn(acc[v][0] * inv, acc[v][1] * inv);
        __half2 h1 = __floats2half2_rn(acc[v][2] * inv, acc[v][3] * inv);
        uint2 o;
        o.x = *(uint32_t*)&h0;
        o.y = *(uint32_t*)&h1;
        orow[v * 32 + lane] = o;
    }
}

// ---------------- fp16 mma.sync fused two-input GEMM + bias + ReLU ---------------
// C = relu(A1@W1^T + A2@W2^T + bias), operands fp16, accum fp32.
// BM=128, BN=128, BK=32 halves; 8 warps 2x4; warp tile 64x32 via m16n8k16.
// Fragments loaded via ldmatrix; 2 CTAs/SM.
#define PADH 40                              // halves per smem row (80 B)
#define TILE_BYTES (128 * PADH * 2)          // 10240
#define STAGE_BYTES (2 * TILE_BYTES)         // 20480 (A + W)
#define STAGE_HALVES (STAGE_BYTES / 2)

template <int K, int SEL>
__device__ __forceinline__ void load_chunk(int c, int m0, int n0, uint32_t sb, int tid) {
    constexpr int NCH = (2 * K) / 32;
    const __half* A1 = (SEL == 0) ? g_m1h  : g_m2h;
    const __half* A2 = (SEL == 0) ? g_xh   : g_h1h;
    const __half* W1 = (SEL == 0) ? g_w1lh : g_w2lh;
    const __half* W2 = (SEL == 0) ? g_w1rh : g_w2rh;

    int st = c & 1;
    int ss = (c >= NCH / 2);
    int k0 = (c - ss * (NCH / 2)) * 32;
    const __half* A = ss ? A2 : A1;
    const __half* W = ss ? W2 : W1;

    int row = tid >> 1;          // 0..127
    int q   = (tid & 1) * 2;     // 16B-chunk 0 or 2

    uint32_t base = sb + (uint32_t)st * STAGE_BYTES;
    uint32_t adst = base + row * (PADH * 2) + q * 16;
    uint32_t wdst = adst + TILE_BYTES;

    int  arow = m0 + row;
    bool v    = (arow < NN);
    int  ar   = v ? arow : 0;
    const __half* asrc = A + (size_t)ar * K + k0 + q * 8;
    const __half* wsrc = W + (size_t)(n0 + row) * K + k0 + q * 8;
    cp16(adst,      asrc,     v);
    cp16(adst + 16, asrc + 8, v);
    cp16(wdst,      wsrc,     true);
    cp16(wdst + 16, wsrc + 8, true);
    asm volatile("cp.async.commit_group;" ::: "memory");
}

template <int K, int SEL>
__global__ void __launch_bounds__(256, 2) k_gemm_h(const float* __restrict__ bias) {
    __half* C = (SEL == 0) ? g_h1h : g_h2h;
    constexpr int NCH = (2 * K) / 32;

    __shared__ __align__(16) __half smem[2 * STAGE_HALVES];
    uint32_t sb = smem_u32(smem);

    const int tid  = threadIdx.x;
    const int warp = tid >> 5;
    const int lane = tid & 31;
    const int g    = lane >> 2;
    const int t    = lane & 3;
    const int m0   = blockIdx.x * 128;
    const int n0   = blockIdx.y * 128;
    const int wm   = warp >> 2;   // 0..1
    const int wn   = warp & 3;    // 0..3

    // ldmatrix lane -> address components
    const int lr  = lane & 15;             // A: row within 16-row tile
    const int kc8 = (lane >> 4) * 8;       // A: col offset 0/8 halves
    const int bl  = lane & 7;              // B: row within 8-col tile
    const int bk8 = ((lane >> 3) & 1) * 8; // B: col offset 0/8 halves

    float acc[4][4][4];
#pragma unroll
    for (int i = 0; i < 4; i++)
#pragma unroll
        for (int j = 0; j < 4; j++)
#pragma unroll
            for (int c = 0; c < 4; c++) acc[i][j][c] = 0.f;

    load_chunk<K, SEL>(0, m0, n0, sb, tid);

    for (int c = 0; c < NCH; c++) {
        if (c + 1 < NCH) {
            load_chunk<K, SEL>(c + 1, m0, n0, sb, tid);
            asm volatile("cp.async.wait_group 1;" ::: "memory");
        } else {
            asm volatile("cp.async.wait_group 0;" ::: "memory");
        }
        __syncthreads();

        uint32_t As_b = sb + (uint32_t)(c & 1) * STAGE_BYTES;
        uint32_t Ws_b = As_b + TILE_BYTES;

#pragma unroll
        for (int ks = 0; ks < 2; ks++) {
            const int kb = ks * 16;
            uint32_t b[4][2];
#pragma unroll
            for (int nt = 0; nt < 4; nt++) {
                uint32_t baddr = Ws_b + ((wn * 32 + nt * 8 + bl) * PADH + kb + bk8) * 2;
                ldsm_x2(b[nt][0], b[nt][1], baddr);
            }
#pragma unroll
            for (int mt = 0; mt < 4; mt++) {
                uint32_t a[4];
                uint32_t aaddr = As_b + ((wm * 64 + mt * 16 + lr) * PADH + kb + kc8) * 2;
                ldsm_x4(a, aaddr);
#pragma unroll
                for (int nt = 0; nt < 4; nt++)
                    mma_f16(acc[mt][nt], a, b[nt]);
            }
        }
        __syncthreads();
    }

    // epilogue: bias + relu -> half2 stores
#pragma unroll
    for (int mt = 0; mt < 4; mt++) {
#pragma unroll
        for (int nt = 0; nt < 4; nt++) {
            int col = n0 + wn * 32 + nt * 8 + 2 * t;
            float b0 = bias[col], b1 = bias[col + 1];
            int r0 = m0 + wm * 64 + mt * 16 + g;
            if (r0 < NN) {
                __half2 h = __floats2half2_rn(fmaxf(acc[mt][nt][0] + b0, 0.f),
                                              fmaxf(acc[mt][nt][1] + b1, 0.f));
                *(uint32_t*)(C + (size_t)r0 * DH + col) = *(uint32_t*)&h;
            }
            int r1 = r0 + 8;
            if (r1 < NN) {
                __half2 h = __floats2half2_rn(fmaxf(acc[mt][nt][2] + b0, 0.f),
                                              fmaxf(acc[mt][nt][3] + b1, 0.f));
                *(uint32_t*)(C + (size_t)r1 * DH + col) = *(uint32_t*)&h;
            }
        }
    }
}

// ---------------- head: out[n] = dot(h2[n,:], head_w) + head_b ----------------
__global__ void k_head(const float* __restrict__ HW, const float* __restrict__ HB,
                       float* __restrict__ out) {
    int gw   = (blockIdx.x * blockDim.x + threadIdx.x) >> 5;
    int lane = threadIdx.x & 31;
    if (gw >= NN) return;
    const uint32_t* h = (const uint32_t*)(g_h2h + (size_t)gw * 256);
    float s = 0.f;
#pragma unroll
    for (int v = 0; v < 4; v++) {
        uint32_t u = h[v * 32 + lane];
        float2 f = __half22float2(*(__half2*)&u);
        int idx = (v * 32 + lane) * 2;
        s += f.x * HW[idx] + f.y * HW[idx + 1];
    }
#pragma unroll
    for (int o = 16; o; o >>= 1) s += __shfl_xor_sync(0xffffffffu, s, o);
    if (lane == 0) out[gw] = s + HB[0];
}

// ---------------- launch ----------------
extern "C" void kernel_launch(void* const* d_in, const int* in_sizes, int n_in,
                              void* d_out, int out_size) {
    const float* x   = (const float*)d_in[0];
    const int*   ei  = (const int*)d_in[1];
    const float* W1l = (const float*)d_in[2];
    const float* b1  = (const float*)d_in[3];
    const float* W1r = (const float*)d_in[4];
    const float* W2l = (const float*)d_in[5];
    const float* b2  = (const float*)d_in[6];
    const float* W2r = (const float*)d_in[7];
    const float* hw  = (const float*)d_in[8];
    const float* hb  = (const float*)d_in[9];
    float* out = (float*)d_out;

    int E = in_sizes[1] / 2;
    const int* srcp = ei;
    const int* dstp = ei + E;

    // conversion + CSR count (deg zeroed in k_round_x, counted in k_prep)
    k_round_x<<<(NN * 128 / 4 + 255) / 256, 256>>>(x);
    k_prep<<<(E + 255) / 256, 256>>>(W1l, W1r, W2l, W2r, dstp, E);

    // CSR offsets + fill
    k_scan1<<<NBLK, SCAN_B>>>();
    k_scan2<<<1, 64>>>();
    k_scan3<<<NBLK, SCAN_B>>>(E);
    k_fill<<<(E + 255) / 256, 256>>>(srcp, dstp, E);

    dim3 gemm_grid((NN + 127) / 128, 2);
    int  agg_blocks = (NN * 32 + 255) / 256;

    // Layer 1
    k_agg<128, 0><<<agg_blocks, 256>>>();
    k_gemm_h<128, 0><<<gemm_grid, 256>>>(b1);

    // Layer 2
    k_agg<256, 1><<<agg_blocks, 256>>>();
    k_gemm_h<256, 1><<<gemm_grid, 256>>>(b2);

    // Head
    k_head<<<agg_blocks, 256>>>(hw, hb, out);
}

// round 9
// speedup vs baseline: 3.5485x; 1.0480x over previous
#include <cuda_runtime.h>
#include <cuda_fp16.h>
#include <cstdint>

#define NN   50000
#define EMAX 800000
#define DH   256
#define SCAN_B 1024
#define NBLK ((NN + SCAN_B - 1) / SCAN_B)   // 49

// ---------------- scratch (device globals; allocation-free) ----------------
__device__ __align__(16) int    g_deg[NN];
__device__ __align__(16) int    g_off[NN + 1];
__device__ __align__(16) int    g_cur[NN];
__device__ __align__(16) int    g_part[NBLK];
__device__ __align__(16) int    g_col[EMAX];
__device__ __align__(16) __half g_xh  [(size_t)NN * 128];   // x in fp16
__device__ __align__(16) __half g_w1lh[256 * 128];
__device__ __align__(16) __half g_w1rh[256 * 128];
__device__ __align__(16) __half g_w2lh[256 * 256];
__device__ __align__(16) __half g_w2rh[256 * 256];
__device__ __align__(16) __half g_m1h [(size_t)NN * 128];
__device__ __align__(16) __half g_h1h [(size_t)NN * 256];
__device__ __align__(16) __half g_m2h [(size_t)NN * 256];

// ---------------- helpers ----------------
__device__ __forceinline__ uint32_t smem_u32(const void* p) {
    uint32_t a;
    asm("{ .reg .u64 t; cvta.to.shared.u64 t, %1; cvt.u32.u64 %0, t; }" : "=r"(a) : "l"(p));
    return a;
}

__device__ __forceinline__ void cp16(uint32_t dst, const void* src, bool v) {
    int sz = v ? 16 : 0;
    asm volatile("cp.async.cg.shared.global [%0], [%1], 16, %2;\n"
                 :: "r"(dst), "l"(src), "r"(sz) : "memory");
}

__device__ __forceinline__ void mma_f16(float c[4], const uint32_t a[4], const uint32_t b[2]) {
    asm volatile(
        "mma.sync.aligned.m16n8k16.row.col.f32.f16.f16.f32 "
        "{%0,%1,%2,%3}, {%4,%5,%6,%7}, {%8,%9}, {%0,%1,%2,%3};\n"
        : "+f"(c[0]), "+f"(c[1]), "+f"(c[2]), "+f"(c[3])
        : "r"(a[0]), "r"(a[1]), "r"(a[2]), "r"(a[3]), "r"(b[0]), "r"(b[1]));
}

__device__ __forceinline__ void ldsm_x4(uint32_t r[4], uint32_t addr) {
    asm volatile("ldmatrix.sync.aligned.m8n8.x4.shared.b16 {%0,%1,%2,%3}, [%4];"
                 : "=r"(r[0]), "=r"(r[1]), "=r"(r[2]), "=r"(r[3]) : "r"(addr));
}

__device__ __forceinline__ void ldsm_x2(uint32_t& r0, uint32_t& r1, uint32_t addr) {
    asm volatile("ldmatrix.sync.aligned.m8n8.x2.shared.b16 {%0,%1}, [%2];"
                 : "=r"(r0), "=r"(r1) : "r"(addr));
}

__device__ __forceinline__ int warp_iscan(int x, int lane) {
#pragma unroll
    for (int o = 1; o < 32; o <<= 1) {
        int y = __shfl_up_sync(0xffffffffu, x, o);
        if (lane >= o) x += y;
    }
    return x;
}

// ---------------- conversion kernels ----------------
__global__ void k_round_x(const float* __restrict__ x) {
    int i = blockIdx.x * blockDim.x + threadIdx.x;
    if (i < NN) g_deg[i] = 0;                 // zero deg BEFORE k_prep's atomics
    if (i < NN * 128 / 4) {
        float4 v = ((const float4*)x)[i];
        __half2 h0 = __floats2half2_rn(v.x, v.y);
        __half2 h1 = __floats2half2_rn(v.z, v.w);
        uint2 o;
        o.x = *(uint32_t*)&h0;
        o.y = *(uint32_t*)&h1;
        ((uint2*)g_xh)[i] = o;
    }
}

// weight conversion + edge degree count, fused (runs after k_round_x)
__global__ void k_prep(const float* __restrict__ W1l, const float* __restrict__ W1r,
                       const float* __restrict__ W2l, const float* __restrict__ W2r,
                       const int* __restrict__ dst, int E) {
    int i = blockIdx.x * blockDim.x + threadIdx.x;
    if (i < 256 * 128) {
        g_w1lh[i] = __float2half_rn(W1l[i]);
        g_w1rh[i] = __float2half_rn(W1r[i]);
    }
    if (i < 256 * 256) {
        g_w2lh[i] = __float2half_rn(W2l[i]);
        g_w2rh[i] = __float2half_rn(W2r[i]);
    }
    if (i < E) atomicAdd(&g_deg[dst[i]], 1);
}

// ---------------- CSR build: 2-phase scan ----------------
// phase 1: per-block exclusive scan + block sums; also zero d_out
__global__ void k_scan1(float* __restrict__ out) {
    __shared__ int wsum[32];
    int t = threadIdx.x, lane = t & 31, w = t >> 5;
    int i = blockIdx.x * SCAN_B + t;
    if (i < NN) out[i] = 0.f;                 // head accumulates into out later
    int v = (i < NN) ? g_deg[i] : 0;
    int x = warp_iscan(v, lane);
    if (lane == 31) wsum[w] = x;
    __syncthreads();
    if (w == 0) {
        int y = wsum[lane];
        int z = warp_iscan(y, lane);
        wsum[lane] = z - y;
    }
    __syncthreads();
    int incl = x + wsum[w];
    if (i < NN) g_off[i] = incl - v;
    if (t == SCAN_B - 1) g_part[blockIdx.x] = incl;
}

// phase 2: every block redundantly scans the NBLK partials, then applies offset
__global__ void k_scan3(int E) {
    __shared__ int spart[64];
    __shared__ int wt[2];
    int t = threadIdx.x, lane = t & 31, w = t >> 5;
    int xv = 0, vv = 0;
    if (t < 64) {
        vv = (t < NBLK) ? g_part[t] : 0;
        xv = warp_iscan(vv, lane);
        if (lane == 31) wt[w] = xv;
    }
    __syncthreads();
    if (t < 64) {
        int off = (w == 1) ? wt[0] : 0;
        spart[t] = xv - vv + off;             // exclusive block offsets
    }
    __syncthreads();
    int i = blockIdx.x * SCAN_B + t;
    if (i < NN) {
        int e = g_off[i] + spart[blockIdx.x];
        g_off[i] = e;
        g_cur[i] = e;
    }
    if (i == 0) g_off[NN] = E;
}

__global__ void k_fill(const int* __restrict__ src, const int* __restrict__ dst, int E) {
    int e = blockIdx.x * blockDim.x + threadIdx.x;
    if (e < E) {
        int p = atomicAdd(&g_cur[dst[e]], 1);
        g_col[p] = src[e];
    }
}

// ---------------- aggregation: one warp per dst; uint2 gathers, fp32 accum ----
template <int D, int SEL>
__global__ void k_agg() {
    const __half* X   = (SEL == 0) ? g_xh  : g_h1h;
    __half*       OUT = (SEL == 0) ? g_m1h : g_m2h;

    int gw   = (blockIdx.x * blockDim.x + threadIdx.x) >> 5;
    int lane = threadIdx.x & 31;
    if (gw >= NN) return;

    constexpr int V2    = D / 128;             // uint2 (4 halves) per lane
    constexpr int BATCH = (D == 128) ? 8 : 4;  // neighbors per inner step
    float acc[V2][4];
#pragma unroll
    for (int v = 0; v < V2; v++)
#pragma unroll
        for (int q = 0; q < 4; q++) acc[v][q] = 0.f;

    int s0 = g_off[gw], s1 = g_off[gw + 1];
    for (int i = s0; i < s1; i += 32) {
        int cnt = min(32, s1 - i);
        int my  = (lane < cnt) ? g_col[i + lane] : 0;
        int j = 0;
        for (; j + BATCH <= cnt; j += BATCH) {
            const uint2* p[BATCH];
#pragma unroll
            for (int b = 0; b < BATCH; b++) {
                int s = __shfl_sync(0xffffffffu, my, j + b);
                p[b] = (const uint2*)(X + (size_t)s * D);
            }
            uint2 u[BATCH][V2];
#pragma unroll
            for (int b = 0; b < BATCH; b++)
#pragma unroll
                for (int v = 0; v < V2; v++) u[b][v] = p[b][v * 32 + lane];
#pragma unroll
            for (int b = 0; b < BATCH; b++)
#pragma unroll
                for (int v = 0; v < V2; v++) {
                    float2 f0 = __half22float2(*(__half2*)&u[b][v].x);
                    float2 f1 = __half22float2(*(__half2*)&u[b][v].y);
                    acc[v][0] += f0.x; acc[v][1] += f0.y;
                    acc[v][2] += f1.x; acc[v][3] += f1.y;
                }
        }
        for (; j < cnt; j++) {
            int s = __shfl_sync(0xffffffffu, my, j);
            const uint2* p = (const uint2*)(X + (size_t)s * D);
#pragma unroll
            for (int v = 0; v < V2; v++) {
                uint2 u = p[v * 32 + lane];
                float2 f0 = __half22float2(*(__half2*)&u.x);
                float2 f1 = __half22float2(*(__half2*)&u.y);
                acc[v][0] += f0.x; acc[v][1] += f0.y;
                acc[v][2] += f1.x; acc[v][3] += f1.y;
            }
        }
    }
    int deg = s1 - s0;
    float inv = 1.0f / (float)max(deg, 1);
    uint2* orow = (uint2*)(OUT + (size_t)gw * D);
#pragma unroll
    for (int v = 0; v < V2; v++) {
        __half2 h0 = __floats2half2_rn(acc[v][0] * inv, acc[v][1] * inv);
        __half2 h1 = __floats2half2_rn(acc[v][2] * inv, acc[v][3] * inv);
        uint2 o;
        o.x = *(uint32_t*)&h0;
        o.y = *(uint32_t*)&h1;
        orow[v * 32 + lane] = o;
    }
}

// ---------------- fp16 mma.sync fused two-input GEMM + bias + ReLU ---------------
// SEL==0: C=h1 (fp16 store). SEL==1: head fused — out[n] += relu(row)·head_w (+hb).
// BM=128, BN=128, BK=32 halves; 8 warps 2x4; warp tile 64x32 via m16n8k16.
#define PADH 40                              // halves per smem row (80 B)
#define TILE_BYTES (128 * PADH * 2)          // 10240
#define STAGE_BYTES (2 * TILE_BYTES)         // 20480 (A + W)
#define STAGE_HALVES (STAGE_BYTES / 2)

template <int K, int SEL>
__device__ __forceinline__ void load_chunk(int c, int m0, int n0, uint32_t sb, int tid) {
    constexpr int NCH = (2 * K) / 32;
    const __half* A1 = (SEL == 0) ? g_m1h  : g_m2h;
    const __half* A2 = (SEL == 0) ? g_xh   : g_h1h;
    const __half* W1 = (SEL == 0) ? g_w1lh : g_w2lh;
    const __half* W2 = (SEL == 0) ? g_w1rh : g_w2rh;

    int st = c & 1;
    int ss = (c >= NCH / 2);
    int k0 = (c - ss * (NCH / 2)) * 32;
    const __half* A = ss ? A2 : A1;
    const __half* W = ss ? W2 : W1;

    int row = tid >> 1;          // 0..127
    int q   = (tid & 1) * 2;     // 16B-chunk 0 or 2

    uint32_t base = sb + (uint32_t)st * STAGE_BYTES;
    uint32_t adst = base + row * (PADH * 2) + q * 16;
    uint32_t wdst = adst + TILE_BYTES;

    int  arow = m0 + row;
    bool v    = (arow < NN);
    int  ar   = v ? arow : 0;
    const __half* asrc = A + (size_t)ar * K + k0 + q * 8;
    const __half* wsrc = W + (size_t)(n0 + row) * K + k0 + q * 8;
    cp16(adst,      asrc,     v);
    cp16(adst + 16, asrc + 8, v);
    cp16(wdst,      wsrc,     true);
    cp16(wdst + 16, wsrc + 8, true);
    asm volatile("cp.async.commit_group;" ::: "memory");
}

template <int K, int SEL>
__global__ void __launch_bounds__(256, 2) k_gemm_h(const float* __restrict__ bias,
                                                   const float* __restrict__ HW,
                                                   const float* __restrict__ HB,
                                                   float* __restrict__ OUTP) {
    constexpr bool HEAD = (SEL == 1);
    constexpr int  NCH  = (2 * K) / 32;

    __shared__ __align__(16) __half smem[2 * STAGE_HALVES];
    __shared__ float sred[128][4];
    uint32_t sb = smem_u32(smem);

    const int tid  = threadIdx.x;
    const int warp = tid >> 5;
    const int lane = tid & 31;
    const int g    = lane >> 2;
    const int t    = lane & 3;
    const int m0   = blockIdx.x * 128;
    const int n0   = blockIdx.y * 128;
    const int wm   = warp >> 2;   // 0..1
    const int wn   = warp & 3;    // 0..3

    // ldmatrix lane -> address components
    const int lr  = lane & 15;             // A: row within 16-row tile
    const int kc8 = (lane >> 4) * 8;       // A: col offset 0/8 halves
    const int bl  = lane & 7;              // B: row within 8-col tile
    const int bk8 = ((lane >> 3) & 1) * 8; // B: col offset 0/8 halves

    float acc[4][4][4];
#pragma unroll
    for (int i = 0; i < 4; i++)
#pragma unroll
        for (int j = 0; j < 4; j++)
#pragma unroll
            for (int c = 0; c < 4; c++) acc[i][j][c] = 0.f;

    load_chunk<K, SEL>(0, m0, n0, sb, tid);

    for (int c = 0; c < NCH; c++) {
        if (c + 1 < NCH) {
            load_chunk<K, SEL>(c + 1, m0, n0, sb, tid);
            asm volatile("cp.async.wait_group 1;" ::: "memory");
        } else {
            asm volatile("cp.async.wait_group 0;" ::: "memory");
        }
        __syncthreads();

        uint32_t As_b = sb + (uint32_t)(c & 1) * STAGE_BYTES;
        uint32_t Ws_b = As_b + TILE_BYTES;

#pragma unroll
        for (int ks = 0; ks < 2; ks++) {
            const int kb = ks * 16;
            uint32_t b[4][2];
#pragma unroll
            for (int nt = 0; nt < 4; nt++) {
                uint32_t baddr = Ws_b + ((wn * 32 + nt * 8 + bl) * PADH + kb + bk8) * 2;
                ldsm_x2(b[nt][0], b[nt][1], baddr);
            }
#pragma unroll
            for (int mt = 0; mt < 4; mt++) {
                uint32_t a[4];
                uint32_t aaddr = As_b + ((wm * 64 + mt * 16 + lr) * PADH + kb + kc8) * 2;
                ldsm_x4(a, aaddr);
#pragma unroll
                for (int nt = 0; nt < 4; nt++)
                    mma_f16(acc[mt][nt], a, b[nt]);
            }
        }
        __syncthreads();
    }

    if constexpr (!HEAD) {
        // epilogue L1: bias + relu -> half2 stores into h1
        __half* C = g_h1h;
#pragma unroll
        for (int mt = 0; mt < 4; mt++) {
#pragma unroll
            for (int nt = 0; nt < 4; nt++) {
                int col = n0 + wn * 32 + nt * 8 + 2 * t;
                float b0 = bias[col], b1 = bias[col + 1];
                int r0 = m0 + wm * 64 + mt * 16 + g;
                if (r0 < NN) {
                    __half2 h = __floats2half2_rn(fmaxf(acc[mt][nt][0] + b0, 0.f),
                                                  fmaxf(acc[mt][nt][1] + b1, 0.f));
                    *(uint32_t*)(C + (size_t)r0 * DH + col) = *(uint32_t*)&h;
                }
                int r1 = r0 + 8;
                if (r1 < NN) {
                    __half2 h = __floats2half2_rn(fmaxf(acc[mt][nt][2] + b0, 0.f),
                                                  fmaxf(acc[mt][nt][3] + b1, 0.f));
                    *(uint32_t*)(C + (size_t)r1 * DH + col) = *(uint32_t*)&h;
                }
            }
        }
    } else {
        // epilogue L2 + head: out[r] += sum_col relu(acc+bias)*hw[col] (+hb by=0)
#pragma unroll
        for (int mt = 0; mt < 4; mt++) {
            float s0 = 0.f, s1 = 0.f;
#pragma unroll
            for (int nt = 0; nt < 4; nt++) {
                int col = n0 + wn * 32 + nt * 8 + 2 * t;
                float b0 = bias[col], b1 = bias[col + 1];
                float w0 = HW[col], w1 = HW[col + 1];
                s0 += fmaxf(acc[mt][nt][0] + b0, 0.f) * w0 +
                      fmaxf(acc[mt][nt][1] + b1, 0.f) * w1;
                s1 += fmaxf(acc[mt][nt][2] + b0, 0.f) * w0 +
                      fmaxf(acc[mt][nt][3] + b1, 0.f) * w1;
            }
            // butterfly over the 4 t-lanes (deterministic)
            s0 += __shfl_xor_sync(0xffffffffu, s0, 1);
            s0 += __shfl_xor_sync(0xffffffffu, s0, 2);
            s1 += __shfl_xor_sync(0xffffffffu, s1, 1);
            s1 += __shfl_xor_sync(0xffffffffu, s1, 2);
            if (t == 0) {
                sred[wm * 64 + mt * 16 + g][wn]     = s0;
                sred[wm * 64 + mt * 16 + g + 8][wn] = s1;
            }
        }
        __syncthreads();
        if (tid < 128) {
            int r = m0 + tid;
            if (r < NN) {
                float v = (sred[tid][0] + sred[tid][1]) + (sred[tid][2] + sred[tid][3]);
                if (blockIdx.y == 0) v += HB[0];
                atomicAdd(&OUTP[r], v);   // 2 commutative contributions -> deterministic
            }
        }
    }
}

// ---------------- launch ----------------
extern "C" void kernel_launch(void* const* d_in, const int* in_sizes, int n_in,
                              void* d_out, int out_size) {
    const float* x   = (const float*)d_in[0];
    const int*   ei  = (const int*)d_in[1];
    const float* W1l = (const float*)d_in[2];
    const float* b1  = (const float*)d_in[3];
    const float* W1r = (const float*)d_in[4];
    const float* W2l = (const float*)d_in[5];
    const float* b2  = (const float*)d_in[6];
    const float* W2r = (const float*)d_in[7];
    const float* hw  = (const float*)d_in[8];
    const float* hb  = (const float*)d_in[9];
    float* out = (float*)d_out;

    int E = in_sizes[1] / 2;
    const int* srcp = ei;
    const int* dstp = ei + E;

    // conversion + CSR count (deg zeroed in k_round_x, counted in k_prep)
    k_round_x<<<(NN * 128 / 4 + 255) / 256, 256>>>(x);
    k_prep<<<(E + 255) / 256, 256>>>(W1l, W1r, W2l, W2r, dstp, E);

    // CSR offsets (2-phase; out zeroed in scan1) + fill
    k_scan1<<<NBLK, SCAN_B>>>(out);
    k_scan3<<<NBLK, SCAN_B>>>(E);
    k_fill<<<(E + 255) / 256, 256>>>(srcp, dstp, E);

    dim3 gemm_grid((NN + 127) / 128, 2);
    int  agg_blocks = (NN * 32 + 255) / 256;

    // Layer 1
    k_agg<128, 0><<<agg_blocks, 256>>>();
    k_gemm_h<128, 0><<<gemm_grid, 256>>>(b1, nullptr, nullptr, nullptr);

    // Layer 2 + head (fused)
    k_agg<256, 1><<<agg_blocks, 256>>>();
    k_gemm_h<256, 1><<<gemm_grid, 256>>>(b2, hw, hb, out);
}

// round 10
// speedup vs baseline: 3.6246x; 1.0214x over previous
#include <cuda_runtime.h>
#include <cuda_fp16.h>
#include <cstdint>

#define NN   50000
#define EMAX 800000
#define DH   256
#define SCAN_B 1024
#define NBLK ((NN + SCAN_B - 1) / SCAN_B)   // 49
#define PUB_FLAG 0x40000000

// ---------------- scratch (device globals; allocation-free) ----------------
__device__ __align__(16) int    g_deg[NN];        // zero at load; self-restored each launch
__device__ __align__(16) int    g_off[NN + 1];
__device__ __align__(16) int    g_cur[NN];
__device__ __align__(16) int    g_col[EMAX];
__device__ volatile int         g_pub[NBLK];      // packed aggregate | PUB_FLAG
__device__ __align__(16) __half g_xh  [(size_t)NN * 128];
__device__ __align__(16) __half g_w1lh[256 * 128];
__device__ __align__(16) __half g_w1rh[256 * 128];
__device__ __align__(16) __half g_w2lh[256 * 256];
__device__ __align__(16) __half g_w2rh[256 * 256];
__device__ __align__(16) __half g_m1h [(size_t)NN * 128];
__device__ __align__(16) __half g_h1h [(size_t)NN * 256];
__device__ __align__(16) __half g_m2h [(size_t)NN * 256];

// ---------------- helpers ----------------
__device__ __forceinline__ uint32_t smem_u32(const void* p) {
    uint32_t a;
    asm("{ .reg .u64 t; cvta.to.shared.u64 t, %1; cvt.u32.u64 %0, t; }" : "=r"(a) : "l"(p));
    return a;
}

__device__ __forceinline__ void cp16(uint32_t dst, const void* src, bool v) {
    int sz = v ? 16 : 0;
    asm volatile("cp.async.cg.shared.global [%0], [%1], 16, %2;\n"
                 :: "r"(dst), "l"(src), "r"(sz) : "memory");
}

__device__ __forceinline__ void mma_f16(float c[4], const uint32_t a[4], const uint32_t b[2]) {
    asm volatile(
        "mma.sync.aligned.m16n8k16.row.col.f32.f16.f16.f32 "
        "{%0,%1,%2,%3}, {%4,%5,%6,%7}, {%8,%9}, {%0,%1,%2,%3};\n"
        : "+f"(c[0]), "+f"(c[1]), "+f"(c[2]), "+f"(c[3])
        : "r"(a[0]), "r"(a[1]), "r"(a[2]), "r"(a[3]), "r"(b[0]), "r"(b[1]));
}

__device__ __forceinline__ void ldsm_x4(uint32_t r[4], uint32_t addr) {
    asm volatile("ldmatrix.sync.aligned.m8n8.x4.shared.b16 {%0,%1,%2,%3}, [%4];"
                 : "=r"(r[0]), "=r"(r[1]), "=r"(r[2]), "=r"(r[3]) : "r"(addr));
}

__device__ __forceinline__ void ldsm_x2(uint32_t& r0, uint32_t& r1, uint32_t addr) {
    asm volatile("ldmatrix.sync.aligned.m8n8.x2.shared.b16 {%0,%1}, [%2];"
                 : "=r"(r0), "=r"(r1) : "r"(addr));
}

__device__ __forceinline__ int warp_iscan(int x, int lane) {
#pragma unroll
    for (int o = 1; o < 32; o <<= 1) {
        int y = __shfl_up_sync(0xffffffffu, x, o);
        if (lane >= o) x += y;
    }
    return x;
}

// ---------------- fused prep: x->fp16, weights->fp16, degree count, flag reset ----
__global__ void k_prep(const float* __restrict__ x,
                       const float* __restrict__ W1l, const float* __restrict__ W1r,
                       const float* __restrict__ W2l, const float* __restrict__ W2r,
                       const int* __restrict__ dst, int E) {
    int i = blockIdx.x * blockDim.x + threadIdx.x;
    if (i < NBLK) g_pub[i] = 0;               // reset scan publication slots
    if (i < NN * 128 / 4) {
        float4 v = ((const float4*)x)[i];
        __half2 h0 = __floats2half2_rn(v.x, v.y);
        __half2 h1 = __floats2half2_rn(v.z, v.w);
        uint2 o;
        o.x = *(uint32_t*)&h0;
        o.y = *(uint32_t*)&h1;
        ((uint2*)g_xh)[i] = o;
    }
    if (i < 256 * 128) {
        g_w1lh[i] = __float2half_rn(W1l[i]);
        g_w1rh[i] = __float2half_rn(W1r[i]);
    }
    if (i < 256 * 256) {
        g_w2lh[i] = __float2half_rn(W2l[i]);
        g_w2rh[i] = __float2half_rn(W2r[i]);
    }
    if (i < E) atomicAdd(&g_deg[dst[i]], 1);  // g_deg pre-zeroed (load init / k_scan)
}

// ---------------- single-pass scan with decoupled lookback ----------------
// Reads g_deg, zeroes it (self-restore), writes g_off/g_cur, zeroes d_out.
__global__ void k_scan(int E, float* __restrict__ out) {
    __shared__ int wsum[32];
    __shared__ int s_prev;
    int t = threadIdx.x, lane = t & 31, w = t >> 5;
    int bid = blockIdx.x;
    int i = bid * SCAN_B + t;

    if (i < NN) out[i] = 0.f;                 // head accumulates into out later
    int v = 0;
    if (i < NN) {
        v = g_deg[i];
        g_deg[i] = 0;                         // self-restore for next launch
    }
    int x = warp_iscan(v, lane);
    if (lane == 31) wsum[w] = x;
    __syncthreads();
    if (w == 0) {
        int y = wsum[lane];
        int z = warp_iscan(y, lane);
        wsum[lane] = z - y;
    }
    __syncthreads();
    int incl = x + wsum[w];

    // publish this block's aggregate (value packed with flag -> single word)
    if (t == SCAN_B - 1) g_pub[bid] = incl | PUB_FLAG;

    // lookback: warp 0 sums all predecessor aggregates
    if (w == 0) {
        int sum = 0;
        for (int b = bid - 1 - lane; b >= 0; b -= 32) {
            int p;
            do { p = g_pub[b]; } while (!(p & PUB_FLAG));
            sum += p & ~PUB_FLAG;
        }
#pragma unroll
        for (int o = 16; o; o >>= 1) sum += __shfl_xor_sync(0xffffffffu, sum, o);
        if (lane == 0) s_prev = sum;
    }
    __syncthreads();

    if (i < NN) {
        int e = incl - v + s_prev;
        g_off[i] = e;
        g_cur[i] = e;
    }
    if (i == 0) g_off[NN] = E;
}

__global__ void k_fill(const int* __restrict__ src, const int* __restrict__ dst, int E) {
    int e = blockIdx.x * blockDim.x + threadIdx.x;
    if (e < E) {
        int p = atomicAdd(&g_cur[dst[e]], 1);
        g_col[p] = src[e];
    }
}

// ---------------- aggregation: one warp per dst; uint2 gathers, fp32 accum ----
template <int D, int SEL>
__global__ void k_agg() {
    const __half* X   = (SEL == 0) ? g_xh  : g_h1h;
    __half*       OUT = (SEL == 0) ? g_m1h : g_m2h;

    int gw   = (blockIdx.x * blockDim.x + threadIdx.x) >> 5;
    int lane = threadIdx.x & 31;
    if (gw >= NN) return;

    constexpr int V2    = D / 128;             // uint2 (4 halves) per lane
    constexpr int BATCH = 8;                   // neighbors per inner step
    float acc[V2][4];
#pragma unroll
    for (int v = 0; v < V2; v++)
#pragma unroll
        for (int q = 0; q < 4; q++) acc[v][q] = 0.f;

    int s0 = g_off[gw], s1 = g_off[gw + 1];
    for (int i = s0; i < s1; i += 32) {
        int cnt = min(32, s1 - i);
        int my  = (lane < cnt) ? g_col[i + lane] : 0;
        int j = 0;
        for (; j + BATCH <= cnt; j += BATCH) {
            const uint2* p[BATCH];
#pragma unroll
            for (int b = 0; b < BATCH; b++) {
                int s = __shfl_sync(0xffffffffu, my, j + b);
                p[b] = (const uint2*)(X + (size_t)s * D);
            }
            uint2 u[BATCH][V2];
#pragma unroll
            for (int b = 0; b < BATCH; b++)
#pragma unroll
                for (int v = 0; v < V2; v++) u[b][v] = p[b][v * 32 + lane];
#pragma unroll
            for (int b = 0; b < BATCH; b++)
#pragma unroll
                for (int v = 0; v < V2; v++) {
                    float2 f0 = __half22float2(*(__half2*)&u[b][v].x);
                    float2 f1 = __half22float2(*(__half2*)&u[b][v].y);
                    acc[v][0] += f0.x; acc[v][1] += f0.y;
                    acc[v][2] += f1.x; acc[v][3] += f1.y;
                }
        }
        for (; j < cnt; j++) {
            int s = __shfl_sync(0xffffffffu, my, j);
            const uint2* p = (const uint2*)(X + (size_t)s * D);
#pragma unroll
            for (int v = 0; v < V2; v++) {
                uint2 u = p[v * 32 + lane];
                float2 f0 = __half22float2(*(__half2*)&u.x);
                float2 f1 = __half22float2(*(__half2*)&u.y);
                acc[v][0] += f0.x; acc[v][1] += f0.y;
                acc[v][2] += f1.x; acc[v][3] += f1.y;
            }
        }
    }
    int deg = s1 - s0;
    float inv = 1.0f / (float)max(deg, 1);
    uint2* orow = (uint2*)(OUT + (size_t)gw * D);
#pragma unroll
    for (int v = 0; v < V2; v++) {
        __half2 h0 = __floats2half2_rn(acc[v][0] * inv, acc[v][1] * inv);
        __half2 h1 = __floats2half2_rn(acc[v][2] * inv, acc[v][3] * inv);
        uint2 o;
        o.x = *(uint32_t*)&h0;
        o.y = *(uint32_t*)&h1;
        orow[v * 32 + lane] = o;
    }
}

// ---------------- fp16 mma.sync fused two-input GEMM + bias + ReLU ---------------
// SEL==0: C=h1 (fp16 store). SEL==1: head fused — out[n] += relu(row)·head_w (+hb).
// BM=128, BN=128, BK=32 halves; 8 warps 2x4; warp tile 64x32 via m16n8k16.
#define PADH 40                              // halves per smem row (80 B)
#define TILE_BYTES (128 * PADH * 2)          // 10240
#define STAGE_BYTES (2 * TILE_BYTES)         // 20480 (A + W)
#define STAGE_HALVES (STAGE_BYTES / 2)

template <int K, int SEL>
__device__ __forceinline__ void load_chunk(int c, int m0, int n0, uint32_t sb, int tid) {
    constexpr int NCH = (2 * K) / 32;
    const __half* A1 = (SEL == 0) ? g_m1h  : g_m2h;
    const __half* A2 = (SEL == 0) ? g_xh   : g_h1h;
    const __half* W1 = (SEL == 0) ? g_w1lh : g_w2lh;
    const __half* W2 = (SEL == 0) ? g_w1rh : g_w2rh;

    int st = c & 1;
    int ss = (c >= NCH / 2);
    int k0 = (c - ss * (NCH / 2)) * 32;
    const __half* A = ss ? A2 : A1;
    const __half* W = ss ? W2 : W1;

    int row = tid >> 1;          // 0..127
    int q   = (tid & 1) * 2;     // 16B-chunk 0 or 2

    uint32_t base = sb + (uint32_t)st * STAGE_BYTES;
    uint32_t adst = base + row * (PADH * 2) + q * 16;
    uint32_t wdst = adst + TILE_BYTES;

    int  arow = m0 + row;
    bool v    = (arow < NN);
    int  ar   = v ? arow : 0;
    const __half* asrc = A + (size_t)ar * K + k0 + q * 8;
    const __half* wsrc = W + (size_t)(n0 + row) * K + k0 + q * 8;
    cp16(adst,      asrc,     v);
    cp16(adst + 16, asrc + 8, v);
    cp16(wdst,      wsrc,     true);
    cp16(wdst + 16, wsrc + 8, true);
    asm volatile("cp.async.commit_group;" ::: "memory");
}

template <int K, int SEL>
__global__ void __launch_bounds__(256, 2) k_gemm_h(const float* __restrict__ bias,
                                                   const float* __restrict__ HW,
                                                   const float* __restrict__ HB,
                                                   float* __restrict__ OUTP) {
    constexpr bool HEAD = (SEL == 1);
    constexpr int  NCH  = (2 * K) / 32;

    __shared__ __align__(16) __half smem[2 * STAGE_HALVES];
    __shared__ float sred[128][4];
    uint32_t sb = smem_u32(smem);

    const int tid  = threadIdx.x;
    const int warp = tid >> 5;
    const int lane = tid & 31;
    const int g    = lane >> 2;
    const int t    = lane & 3;
    const int m0   = blockIdx.x * 128;
    const int n0   = blockIdx.y * 128;
    const int wm   = warp >> 2;   // 0..1
    const int wn   = warp & 3;    // 0..3

    const int lr  = lane & 15;
    const int kc8 = (lane >> 4) * 8;
    const int bl  = lane & 7;
    const int bk8 = ((lane >> 3) & 1) * 8;

    float acc[4][4][4];
#pragma unroll
    for (int i = 0; i < 4; i++)
#pragma unroll
        for (int j = 0; j < 4; j++)
#pragma unroll
            for (int c = 0; c < 4; c++) acc[i][j][c] = 0.f;

    load_chunk<K, SEL>(0, m0, n0, sb, tid);

    for (int c = 0; c < NCH; c++) {
        if (c + 1 < NCH) {
            load_chunk<K, SEL>(c + 1, m0, n0, sb, tid);
            asm volatile("cp.async.wait_group 1;" ::: "memory");
        } else {
            asm volatile("cp.async.wait_group 0;" ::: "memory");
        }
        __syncthreads();

        uint32_t As_b = sb + (uint32_t)(c & 1) * STAGE_BYTES;
        uint32_t Ws_b = As_b + TILE_BYTES;

#pragma unroll
        for (int ks = 0; ks < 2; ks++) {
            const int kb = ks * 16;
            uint32_t b[4][2];
#pragma unroll
            for (int nt = 0; nt < 4; nt++) {
                uint32_t baddr = Ws_b + ((wn * 32 + nt * 8 + bl) * PADH + kb + bk8) * 2;
                ldsm_x2(b[nt][0], b[nt][1], baddr);
            }
#pragma unroll
            for (int mt = 0; mt < 4; mt++) {
                uint32_t a[4];
                uint32_t aaddr = As_b + ((wm * 64 + mt * 16 + lr) * PADH + kb + kc8) * 2;
                ldsm_x4(a, aaddr);
#pragma unroll
                for (int nt = 0; nt < 4; nt++)
                    mma_f16(acc[mt][nt], a, b[nt]);
            }
        }
        __syncthreads();
    }

    if constexpr (!HEAD) {
        __half* C = g_h1h;
#pragma unroll
        for (int mt = 0; mt < 4; mt++) {
#pragma unroll
            for (int nt = 0; nt < 4; nt++) {
                int col = n0 + wn * 32 + nt * 8 + 2 * t;
                float b0 = bias[col], b1 = bias[col + 1];
                int r0 = m0 + wm * 64 + mt * 16 + g;
                if (r0 < NN) {
                    __half2 h = __floats2half2_rn(fmaxf(acc[mt][nt][0] + b0, 0.f),
                                                  fmaxf(acc[mt][nt][1] + b1, 0.f));
                    *(uint32_t*)(C + (size_t)r0 * DH + col) = *(uint32_t*)&h;
                }
                int r1 = r0 + 8;
                if (r1 < NN) {
                    __half2 h = __floats2half2_rn(fmaxf(acc[mt][nt][2] + b0, 0.f),
                                                  fmaxf(acc[mt][nt][3] + b1, 0.f));
                    *(uint32_t*)(C + (size_t)r1 * DH + col) = *(uint32_t*)&h;
                }
            }
        }
    } else {
#pragma unroll
        for (int mt = 0; mt < 4; mt++) {
            float s0 = 0.f, s1 = 0.f;
#pragma unroll
            for (int nt = 0; nt < 4; nt++) {
                int col = n0 + wn * 32 + nt * 8 + 2 * t;
                float b0 = bias[col], b1 = bias[col + 1];
                float w0 = HW[col], w1 = HW[col + 1];
                s0 += fmaxf(acc[mt][nt][0] + b0, 0.f) * w0 +
                      fmaxf(acc[mt][nt][1] + b1, 0.f) * w1;
                s1 += fmaxf(acc[mt][nt][2] + b0, 0.f) * w0 +
                      fmaxf(acc[mt][nt][3] + b1, 0.f) * w1;
            }
            s0 += __shfl_xor_sync(0xffffffffu, s0, 1);
            s0 += __shfl_xor_sync(0xffffffffu, s0, 2);
            s1 += __shfl_xor_sync(0xffffffffu, s1, 1);
            s1 += __shfl_xor_sync(0xffffffffu, s1, 2);
            if (t == 0) {
                sred[wm * 64 + mt * 16 + g][wn]     = s0;
                sred[wm * 64 + mt * 16 + g + 8][wn] = s1;
            }
        }
        __syncthreads();
        if (tid < 128) {
            int r = m0 + tid;
            if (r < NN) {
                float v = (sred[tid][0] + sred[tid][1]) + (sred[tid][2] + sred[tid][3]);
                if (blockIdx.y == 0) v += HB[0];
                atomicAdd(&OUTP[r], v);   // 2 commutative contributions -> deterministic
            }
        }
    }
}

// ---------------- launch ----------------
extern "C" void kernel_launch(void* const* d_in, const int* in_sizes, int n_in,
                              void* d_out, int out_size) {
    const float* x   = (const float*)d_in[0];
    const int*   ei  = (const int*)d_in[1];
    const float* W1l = (const float*)d_in[2];
    const float* b1  = (const float*)d_in[3];
    const float* W1r = (const float*)d_in[4];
    const float* W2l = (const float*)d_in[5];
    const float* b2  = (const float*)d_in[6];
    const float* W2r = (const float*)d_in[7];
    const float* hw  = (const float*)d_in[8];
    const float* hb  = (const float*)d_in[9];
    float* out = (float*)d_out;

    int E = in_sizes[1] / 2;
    const int* srcp = ei;
    const int* dstp = ei + E;

    // fused conversion + degree count + scan-flag reset
    k_prep<<<(NN * 128 / 4 + 255) / 256, 256>>>(x, W1l, W1r, W2l, W2r, dstp, E);

    // single-pass CSR offsets (also zeroes d_out and g_deg) + fill
    k_scan<<<NBLK, SCAN_B>>>(E, out);
    k_fill<<<(E + 255) / 256, 256>>>(srcp, dstp, E);

    dim3 gemm_grid((NN + 127) / 128, 2);
    int  agg_blocks = (NN * 32 + 255) / 256;

    // Layer 1
    k_agg<128, 0><<<agg_blocks, 256>>>();
    k_gemm_h<128, 0><<<gemm_grid, 256>>>(b1, nullptr, nullptr, nullptr);

    // Layer 2 + head (fused)
    k_agg<256, 1><<<agg_blocks, 256>>>();
    k_gemm_h<256, 1><<<gemm_grid, 256>>>(b2, hw, hb, out);
}

// round 12
// speedup vs baseline: 3.7243x; 1.0275x over previous
#include <cuda_runtime.h>
#include <cuda_fp16.h>
#include <cstdint>

#define NN   50000
#define EMAX 800000
#define DH   256
#define SCAN_B 1024
#define NBLK ((NN + SCAN_B - 1) / SCAN_B)   // 49
#define PUB_FLAG 0x40000000

// ---------------- scratch (device globals; allocation-free) ----------------
__device__ __align__(16) int    g_deg[NN];        // zero at load; self-restored each launch
__device__ __align__(16) int    g_off[NN + 1];
__device__ __align__(16) int    g_cur[NN];
__device__ __align__(16) int    g_col[EMAX];
__device__ volatile int         g_pub[NBLK];      // packed aggregate | PUB_FLAG
__device__ __align__(16) __half g_xh  [(size_t)NN * 128];
__device__ __align__(16) __half g_w1lh[256 * 128];
__device__ __align__(16) __half g_w1rh[256 * 128];
__device__ __align__(16) __half g_w2lh[256 * 256];
__device__ __align__(16) __half g_w2rh[256 * 256];
__device__ __align__(16) __half g_m1h [(size_t)NN * 128];
__device__ __align__(16) __half g_h1h [(size_t)NN * 256];
__device__ __align__(16) __half g_m2h [(size_t)NN * 256];

// ---------------- helpers ----------------
__device__ __forceinline__ uint32_t smem_u32(const void* p) {
    uint32_t a;
    asm("{ .reg .u64 t; cvta.to.shared.u64 t, %1; cvt.u32.u64 %0, t; }" : "=r"(a) : "l"(p));
    return a;
}

__device__ __forceinline__ void cp16(uint32_t dst, const void* src, bool v) {
    int sz = v ? 16 : 0;
    asm volatile("cp.async.cg.shared.global [%0], [%1], 16, %2;\n"
                 :: "r"(dst), "l"(src), "r"(sz) : "memory");
}

__device__ __forceinline__ void mma_f16(float c[4], const uint32_t a[4], const uint32_t b[2]) {
    asm volatile(
        "mma.sync.aligned.m16n8k16.row.col.f32.f16.f16.f32 "
        "{%0,%1,%2,%3}, {%4,%5,%6,%7}, {%8,%9}, {%0,%1,%2,%3};\n"
        : "+f"(c[0]), "+f"(c[1]), "+f"(c[2]), "+f"(c[3])
        : "r"(a[0]), "r"(a[1]), "r"(a[2]), "r"(a[3]), "r"(b[0]), "r"(b[1]));
}

__device__ __forceinline__ void ldsm_x4(uint32_t r[4], uint32_t addr) {
    asm volatile("ldmatrix.sync.aligned.m8n8.x4.shared.b16 {%0,%1,%2,%3}, [%4];"
                 : "=r"(r[0]), "=r"(r[1]), "=r"(r[2]), "=r"(r[3]) : "r"(addr));
}

__device__ __forceinline__ void ldsm_x2(uint32_t& r0, uint32_t& r1, uint32_t addr) {
    asm volatile("ldmatrix.sync.aligned.m8n8.x2.shared.b16 {%0,%1}, [%2];"
                 : "=r"(r0), "=r"(r1) : "r"(addr));
}

__device__ __forceinline__ int warp_iscan(int x, int lane) {
#pragma unroll
    for (int o = 1; o < 32; o <<= 1) {
        int y = __shfl_up_sync(0xffffffffu, x, o);
        if (lane >= o) x += y;
    }
    return x;
}

// ---------------- fused prep: x->fp16, weights->fp16, degree count, flag reset ----
__global__ void k_prep(const float* __restrict__ x,
                       const float* __restrict__ W1l, const float* __restrict__ W1r,
                       const float* __restrict__ W2l, const float* __restrict__ W2r,
                       const int* __restrict__ dst, int E) {
    int i = blockIdx.x * blockDim.x + threadIdx.x;
    if (i < NBLK) g_pub[i] = 0;               // reset scan publication slots
    if (i < NN * 128 / 4) {
        float4 v = ((const float4*)x)[i];
        __half2 h0 = __floats2half2_rn(v.x, v.y);
        __half2 h1 = __floats2half2_rn(v.z, v.w);
        uint2 o;
        o.x = *(uint32_t*)&h0;
        o.y = *(uint32_t*)&h1;
        ((uint2*)g_xh)[i] = o;
    }
    if (i < 256 * 128) {
        g_w1lh[i] = __float2half_rn(W1l[i]);
        g_w1rh[i] = __float2half_rn(W1r[i]);
    }
    if (i < 256 * 256) {
        g_w2lh[i] = __float2half_rn(W2l[i]);
        g_w2rh[i] = __float2half_rn(W2r[i]);
    }
    if (i < E) atomicAdd(&g_deg[dst[i]], 1);  // g_deg pre-zeroed (load init / k_scan)
}

// ---------------- single-pass scan with decoupled lookback ----------------
__global__ void k_scan(int E, float* __restrict__ out) {
    __shared__ int wsum[32];
    __shared__ int s_prev;
    int t = threadIdx.x, lane = t & 31, w = t >> 5;
    int bid = blockIdx.x;
    int i = bid * SCAN_B + t;

    if (i < NN) out[i] = 0.f;                 // head accumulates into out later
    int v = 0;
    if (i < NN) {
        v = g_deg[i];
        g_deg[i] = 0;                         // self-restore for next launch
    }
    int x = warp_iscan(v, lane);
    if (lane == 31) wsum[w] = x;
    __syncthreads();
    if (w == 0) {
        int y = wsum[lane];
        int z = warp_iscan(y, lane);
        wsum[lane] = z - y;
    }
    __syncthreads();
    int incl = x + wsum[w];

    if (t == SCAN_B - 1) g_pub[bid] = incl | PUB_FLAG;

    if (w == 0) {
        int sum = 0;
        for (int b = bid - 1 - lane; b >= 0; b -= 32) {
            int p;
            do { p = g_pub[b]; } while (!(p & PUB_FLAG));
            sum += p & ~PUB_FLAG;
        }
#pragma unroll
        for (int o = 16; o; o >>= 1) sum += __shfl_xor_sync(0xffffffffu, sum, o);
        if (lane == 0) s_prev = sum;
    }
    __syncthreads();

    if (i < NN) {
        int e = incl - v + s_prev;
        g_off[i] = e;
        g_cur[i] = e;
    }
    if (i == 0) g_off[NN] = E;
}

__global__ void k_fill(const int* __restrict__ src, const int* __restrict__ dst, int E) {
    int e = blockIdx.x * blockDim.x + threadIdx.x;
    if (e < E) {
        int p = atomicAdd(&g_cur[dst[e]], 1);
        g_col[p] = src[e];
    }
}

// ---------------- aggregation: one warp per dst; pairwise half2 accumulate ----
template <int D, int SEL>
__global__ void k_agg() {
    const __half* X   = (SEL == 0) ? g_xh  : g_h1h;
    __half*       OUT = (SEL == 0) ? g_m1h : g_m2h;

    int gw   = (blockIdx.x * blockDim.x + threadIdx.x) >> 5;
    int lane = threadIdx.x & 31;
    if (gw >= NN) return;

    constexpr int V2    = D / 128;             // uint2 (4 halves) per lane
    constexpr int BATCH = 8;                   // neighbors per inner step
    float acc[V2][4];
#pragma unroll
    for (int v = 0; v < V2; v++)
#pragma unroll
        for (int q = 0; q < 4; q++) acc[v][q] = 0.f;

    int s0 = g_off[gw], s1 = g_off[gw + 1];
    for (int i = s0; i < s1; i += 32) {
        int cnt = min(32, s1 - i);
        int my  = (lane < cnt) ? g_col[i + lane] : 0;
        int j = 0;
        for (; j + BATCH <= cnt; j += BATCH) {
            const uint2* p[BATCH];
#pragma unroll
            for (int b = 0; b < BATCH; b++) {
                int s = __shfl_sync(0xffffffffu, my, j + b);
                p[b] = (const uint2*)(X + (size_t)s * D);
            }
            uint2 u[BATCH][V2];
#pragma unroll
            for (int b = 0; b < BATCH; b++)
#pragma unroll
                for (int v = 0; v < V2; v++) u[b][v] = p[b][v * 32 + lane];
            // pairwise half2 add (1 rounding at element magnitude), then fp32 accum
#pragma unroll
            for (int b = 0; b < BATCH; b += 2)
#pragma unroll
                for (int v = 0; v < V2; v++) {
                    __half2 px = __hadd2(*(__half2*)&u[b][v].x, *(__half2*)&u[b + 1][v].x);
                    __half2 py = __hadd2(*(__half2*)&u[b][v].y, *(__half2*)&u[b + 1][v].y);
                    float2 f0 = __half22float2(px);
                    float2 f1 = __half22float2(py);
                    acc[v][0] += f0.x; acc[v][1] += f0.y;
                    acc[v][2] += f1.x; acc[v][3] += f1.y;
                }
        }
        for (; j < cnt; j++) {                 // tail: exact fp32 path
            int s = __shfl_sync(0xffffffffu, my, j);
            const uint2* p = (const uint2*)(X + (size_t)s * D);
#pragma unroll
            for (int v = 0; v < V2; v++) {
                uint2 u = p[v * 32 + lane];
                float2 f0 = __half22float2(*(__half2*)&u.x);
                float2 f1 = __half22float2(*(__half2*)&u.y);
                acc[v][0] += f0.x; acc[v][1] += f0.y;
                acc[v][2] += f1.x; acc[v][3] += f1.y;
            }
        }
    }
    int deg = s1 - s0;
    float inv = 1.0f / (float)max(deg, 1);
    uint2* orow = (uint2*)(OUT + (size_t)gw * D);
#pragma unroll
    for (int v = 0; v < V2; v++) {
        __half2 h0 = __floats2half2_rn(acc[v][0] * inv, acc[v][1] * inv);
        __half2 h1 = __floats2half2_rn(acc[v][2] * inv, acc[v][3] * inv);
        uint2 o;
        o.x = *(uint32_t*)&h0;
        o.y = *(uint32_t*)&h1;
        orow[v * 32 + lane] = o;
    }
}

// ---------------- fp16 mma.sync fused two-input GEMM + bias + ReLU ---------------
// SEL==0: C=h1 (fp16 store). SEL==1: head fused — out[n] += relu(row)·head_w (+hb).
#define PADH 40                              // halves per smem row (80 B)
#define TILE_BYTES (128 * PADH * 2)          // 10240
#define STAGE_BYTES (2 * TILE_BYTES)         // 20480 (A + W)
#define STAGE_HALVES (STAGE_BYTES / 2)

template <int K, int SEL>
__device__ __forceinline__ void load_chunk(int c, int m0, int n0, uint32_t sb, int tid) {
    constexpr int NCH = (2 * K) / 32;
    const __half* A1 = (SEL == 0) ? g_m1h  : g_m2h;
    const __half* A2 = (SEL == 0) ? g_xh   : g_h1h;
    const __half* W1 = (SEL == 0) ? g_w1lh : g_w2lh;
    const __half* W2 = (SEL == 0) ? g_w1rh : g_w2rh;

    int st = c & 1;
    int ss = (c >= NCH / 2);
    int k0 = (c - ss * (NCH / 2)) * 32;
    const __half* A = ss ? A2 : A1;
    const __half* W = ss ? W2 : W1;

    int row = tid >> 1;          // 0..127
    int q   = (tid & 1) * 2;     // 16B-chunk 0 or 2

    uint32_t base = sb + (uint32_t)st * STAGE_BYTES;
    uint32_t adst = base + row * (PADH * 2) + q * 16;
    uint32_t wdst = adst + TILE_BYTES;

    int  arow = m0 + row;
    bool v    = (arow < NN);
    int  ar   = v ? arow : 0;
    const __half* asrc = A + (size_t)ar * K + k0 + q * 8;
    const __half* wsrc = W + (size_t)(n0 + row) * K + k0 + q * 8;
    cp16(adst,      asrc,     v);
    cp16(adst + 16, asrc + 8, v);
    cp16(wdst,      wsrc,     true);
    cp16(wdst + 16, wsrc + 8, true);
    asm volatile("cp.async.commit_group;" ::: "memory");
}

template <int K, int SEL>
__global__ void __launch_bounds__(256, 2) k_gemm_h(const float* __restrict__ bias,
                                                   const float* __restrict__ HW,
                                                   const float* __restrict__ HB,
                                                   float* __restrict__ OUTP) {
    constexpr bool HEAD = (SEL == 1);
    constexpr int  NCH  = (2 * K) / 32;

    __shared__ __align__(16) __half smem[2 * STAGE_HALVES];
    __shared__ float sred[128][4];
    uint32_t sb = smem_u32(smem);

    const int tid  = threadIdx.x;
    const int warp = tid >> 5;
    const int lane = tid & 31;
    const int g    = lane >> 2;
    const int t    = lane & 3;
    const int m0   = blockIdx.x * 128;
    const int n0   = blockIdx.y * 128;
    const int wm   = warp >> 2;   // 0..1
    const int wn   = warp & 3;    // 0..3

    const int lr  = lane & 15;
    const int kc8 = (lane >> 4) * 8;
    const int bl  = lane & 7;
    const int bk8 = ((lane >> 3) & 1) * 8;

    float acc[4][4][4];
#pragma unroll
    for (int i = 0; i < 4; i++)
#pragma unroll
        for (int j = 0; j < 4; j++)
#pragma unroll
            for (int c = 0; c < 4; c++) acc[i][j][c] = 0.f;

    load_chunk<K, SEL>(0, m0, n0, sb, tid);

    for (int c = 0; c < NCH; c++) {
        if (c + 1 < NCH) {
            load_chunk<K, SEL>(c + 1, m0, n0, sb, tid);
            asm volatile("cp.async.wait_group 1;" ::: "memory");
        } else {
            asm volatile("cp.async.wait_group 0;" ::: "memory");
        }
        __syncthreads();

        uint32_t As_b = sb + (uint32_t)(c & 1) * STAGE_BYTES;
        uint32_t Ws_b = As_b + TILE_BYTES;

#pragma unroll
        for (int ks = 0; ks < 2; ks++) {
            const int kb = ks * 16;
            uint32_t b[4][2];
#pragma unroll
            for (int nt = 0; nt < 4; nt++) {
                uint32_t baddr = Ws_b + ((wn * 32 + nt * 8 + bl) * PADH + kb + bk8) * 2;
                ldsm_x2(b[nt][0], b[nt][1], baddr);
            }
#pragma unroll
            for (int mt = 0; mt < 4; mt++) {
                uint32_t a[4];
                uint32_t aaddr = As_b + ((wm * 64 + mt * 16 + lr) * PADH + kb + kc8) * 2;
                ldsm_x4(a, aaddr);
#pragma unroll
                for (int nt = 0; nt < 4; nt++)
                    mma_f16(acc[mt][nt], a, b[nt]);
            }
        }
        __syncthreads();
    }

    if constexpr (!HEAD) {
        __half* C = g_h1h;
#pragma unroll
        for (int mt = 0; mt < 4; mt++) {
#pragma unroll
            for (int nt = 0; nt < 4; nt++) {
                int col = n0 + wn * 32 + nt * 8 + 2 * t;
                float b0 = bias[col], b1 = bias[col + 1];
                int r0 = m0 + wm * 64 + mt * 16 + g;
                if (r0 < NN) {
                    __half2 h = __floats2half2_rn(fmaxf(acc[mt][nt][0] + b0, 0.f),
                                                  fmaxf(acc[mt][nt][1] + b1, 0.f));
                    *(uint32_t*)(C + (size_t)r0 * DH + col) = *(uint32_t*)&h;
                }
                int r1 = r0 + 8;
                if (r1 < NN) {
                    __half2 h = __floats2half2_rn(fmaxf(acc[mt][nt][2] + b0, 0.f),
                                                  fmaxf(acc[mt][nt][3] + b1, 0.f));
                    *(uint32_t*)(C + (size_t)r1 * DH + col) = *(uint32_t*)&h;
                }
            }
        }
    } else {
#pragma unroll
        for (int mt = 0; mt < 4; mt++) {
            float s0 = 0.f, s1 = 0.f;
#pragma unroll
            for (int nt = 0; nt < 4; nt++) {
                int col = n0 + wn * 32 + nt * 8 + 2 * t;
                float b0 = bias[col], b1 = bias[col + 1];
                float w0 = HW[col], w1 = HW[col + 1];
                s0 += fmaxf(acc[mt][nt][0] + b0, 0.f) * w0 +
                      fmaxf(acc[mt][nt][1] + b1, 0.f) * w1;
                s1 += fmaxf(acc[mt][nt][2] + b0, 0.f) * w0 +
                      fmaxf(acc[mt][nt][3] + b1, 0.f) * w1;
            }
            s0 += __shfl_xor_sync(0xffffffffu, s0, 1);
            s0 += __shfl_xor_sync(0xffffffffu, s0, 2);
            s1 += __shfl_xor_sync(0xffffffffu, s1, 1);
            s1 += __shfl_xor_sync(0xffffffffu, s1, 2);
            if (t == 0) {
                sred[wm * 64 + mt * 16 + g][wn]     = s0;
                sred[wm * 64 + mt * 16 + g + 8][wn] = s1;
            }
        }
        __syncthreads();
        if (tid < 128) {
            int r = m0 + tid;
            if (r < NN) {
                float v = (sred[tid][0] + sred[tid][1]) + (sred[tid][2] + sred[tid][3]);
                if (blockIdx.y == 0) v += HB[0];
                atomicAdd(&OUTP[r], v);   // 2 commutative contributions -> deterministic
            }
        }
    }
}

// ---------------- launch ----------------
extern "C" void kernel_launch(void* const* d_in, const int* in_sizes, int n_in,
                              void* d_out, int out_size) {
    const float* x   = (const float*)d_in[0];
    const int*   ei  = (const int*)d_in[1];
    const float* W1l = (const float*)d_in[2];
    const float* b1  = (const float*)d_in[3];
    const float* W1r = (const float*)d_in[4];
    const float* W2l = (const float*)d_in[5];
    const float* b2  = (const float*)d_in[6];
    const float* W2r = (const float*)d_in[7];
    const float* hw  = (const float*)d_in[8];
    const float* hb  = (const float*)d_in[9];
    float* out = (float*)d_out;

    int E = in_sizes[1] / 2;
    const int* srcp = ei;
    const int* dstp = ei + E;

    // fused conversion + degree count + scan-flag reset
    k_prep<<<(NN * 128 / 4 + 255) / 256, 256>>>(x, W1l, W1r, W2l, W2r, dstp, E);

    // single-pass CSR offsets (also zeroes d_out and g_deg) + fill
    k_scan<<<NBLK, SCAN_B>>>(E, out);
    k_fill<<<(E + 255) / 256, 256>>>(srcp, dstp, E);

    dim3 gemm_grid((NN + 127) / 128, 2);
    int  agg_blocks = (NN * 32 + 255) / 256;

    // Layer 1
    k_agg<128, 0><<<agg_blocks, 256>>>();
    k_gemm_h<128, 0><<<gemm_grid, 256>>>(b1, nullptr, nullptr, nullptr);

    // Layer 2 + head (fused)
    k_agg<256, 1><<<agg_blocks, 256>>>();
    k_gemm_h<256, 1><<<gemm_grid, 256>>>(b2, hw, hb, out);
}